// round 3
// baseline (speedup 1.0000x reference)
#include <cuda_runtime.h>

// Problem constants
#define NPTS 4096
#define DIMK 256
#define NEPS 4
#define NWRD 128              // 4096 bits / 32 per row
#define NN   (NPTS*NPTS)      // 16777216

// Output layout (float32, concatenated in reference return order)
#define LOSS_OFF 0u
#define VM_OFF   4096u
#define A_OFF    20480u                      // 4096 + 4*4096
#define TRI_OFF  (20480u + 67108864u)        // + E*N*N

// ---------------- device scratch (globals: allocation-free rule) ----------
__device__ float         g_d[NN];                 // 67 MB distance matrix
__device__ unsigned      g_abits[NEPS][NPTS*NWRD];// 8 MB packed adjacency
__device__ float         g_sq[NPTS];
__device__ unsigned char g_vmb[NPTS];             // 4 mask bits per point
__device__ unsigned      g_hist[NEPS][2048];      // radix-select histograms
__device__ unsigned      g_pref[NEPS];
__device__ unsigned      g_k[NEPS];
__device__ unsigned      g_thrbits[NEPS];
__device__ int           g_done[NEPS];

// ---------------- Stage 1: losses, vmask, sqnorms --------------------------
// Replicates the hypothesized XLA GPU row-reduction order bit-exactly:
// one warp per row; each lane FMA-accumulates 8 lane-strided elements
// (stride 32, ascending), then a shfl_down tree (16,8,4,2,1).
__global__ void prep_kernel(const float* __restrict__ residue,
                            const float* __restrict__ constraint,
                            const float* __restrict__ eps,
                            float* __restrict__ out) {
    int gw   = (blockIdx.x * blockDim.x + threadIdx.x) >> 5;   // row id
    int lane = threadIdx.x & 31;
    if (gw >= NPTS) return;

    const float* __restrict__ c = constraint + (unsigned)gw * DIMK;
    const float* __restrict__ r = residue    + (unsigned)gw * DIMK;

    float s_sq = 0.f, s_ls = 0.f;
    #pragma unroll
    for (int j = 0; j < 8; j++) {
        float cv = c[lane + 32 * j];
        float rv = r[lane + 32 * j];
        s_sq = __fmaf_rn(cv, cv, s_sq);
        float df = __fadd_rn(rv, -cv);          // exact-rounded subtraction
        s_ls = __fmaf_rn(df, df, s_ls);
    }
    #pragma unroll
    for (int o = 16; o > 0; o >>= 1) {
        s_sq = __fadd_rn(s_sq, __shfl_down_sync(0xffffffffu, s_sq, o));
        s_ls = __fadd_rn(s_ls, __shfl_down_sync(0xffffffffu, s_ls, o));
    }

    if (lane == 0) {
        g_sq[gw] = s_sq;
        float loss = __fsqrt_rn(s_ls);
        out[LOSS_OFF + gw] = loss;
        unsigned char mb = 0;
        #pragma unroll
        for (int e = 0; e < NEPS; e++) {
            bool m = loss <= eps[e];
            mb |= (unsigned char)((m ? 1 : 0) << e);
            out[VM_OFF + (unsigned)e * NPTS + gw] = m ? 1.f : 0.f;
        }
        g_vmb[gw] = mb;
    }
}

// ---------------- Stage 2: pairwise distances (fp32 SGEMM) ----------------
// Strict ascending-k FMA chain per output element (cuBLAS SGEMM order).
// Epilogue replicates ((sq_i + sq_j) - 2*G) with exact-rounded ops.
// Diagonal computed NATURALLY (no zeroing): tiny positive d[i,i] values
// must enter the median's valid set exactly as in the reference.
__global__ void __launch_bounds__(256)
dist_kernel(const float* __restrict__ C) {
    __shared__ float shI[32 * 65];
    __shared__ float shJ[32 * 65];
    int bi = blockIdx.y, bj = blockIdx.x;
    int i0 = bi * 64, j0 = bj * 64;
    int tx = threadIdx.x, ty = threadIdx.y;
    int tid = ty * 16 + tx;
    float acc[4][4] = {};

    for (int k0 = 0; k0 < DIMK; k0 += 32) {
        #pragma unroll
        for (int r = 0; r < 2; r++) {
            int q   = tid + r * 256;
            int row = q >> 3;          // 8 float4 per 32-wide row
            int kq  = q & 7;
            float4 vI = *(const float4*)&C[(i0 + row) * DIMK + k0 + kq * 4];
            float4 vJ = *(const float4*)&C[(j0 + row) * DIMK + k0 + kq * 4];
            int b = kq * 4;
            shI[(b + 0) * 65 + row] = vI.x; shI[(b + 1) * 65 + row] = vI.y;
            shI[(b + 2) * 65 + row] = vI.z; shI[(b + 3) * 65 + row] = vI.w;
            shJ[(b + 0) * 65 + row] = vJ.x; shJ[(b + 1) * 65 + row] = vJ.y;
            shJ[(b + 2) * 65 + row] = vJ.z; shJ[(b + 3) * 65 + row] = vJ.w;
        }
        __syncthreads();
        #pragma unroll
        for (int kk = 0; kk < 32; kk++) {
            float ai[4], bb[4];
            #pragma unroll
            for (int a = 0; a < 4; a++) ai[a] = shI[kk * 65 + ty * 4 + a];
            #pragma unroll
            for (int b = 0; b < 4; b++) bb[b] = shJ[kk * 65 + tx * 4 + b];
            #pragma unroll
            for (int a = 0; a < 4; a++)
                #pragma unroll
                for (int b = 0; b < 4; b++)
                    acc[a][b] = __fmaf_rn(ai[a], bb[b], acc[a][b]);
        }
        __syncthreads();
    }

    float sqi[4], sqj[4];
    #pragma unroll
    for (int a = 0; a < 4; a++) sqi[a] = g_sq[i0 + ty * 4 + a];
    #pragma unroll
    for (int b = 0; b < 4; b++) sqj[b] = g_sq[j0 + tx * 4 + b];

    #pragma unroll
    for (int a = 0; a < 4; a++) {
        int i = i0 + ty * 4 + a;
        float v[4];
        #pragma unroll
        for (int b = 0; b < 4; b++) {
            float t1 = __fadd_rn(sqi[a], sqj[b]);              // sq_i + sq_j
            float g2 = __fmul_rn(2.0f, acc[a][b]);             // 2*G (exact)
            float d2 = __fadd_rn(t1, -g2);                     // rounded sub
            v[b] = __fsqrt_rn(fmaxf(d2, 0.0f));
        }
        *(float4*)&g_d[(unsigned)i * NPTS + j0 + tx * 4] =
            make_float4(v[0], v[1], v[2], v[3]);
    }
}

// ---------------- Stage 3: radix select of the lower median ---------------
template<int PASS>
__global__ void hist_kernel() {
    __shared__ unsigned sh[NEPS * 2048];
    int tid = threadIdx.x;
    for (int q = tid; q < NEPS * 2048; q += 256) sh[q] = 0;
    __syncthreads();

    unsigned pref[NEPS];
    #pragma unroll
    for (int e = 0; e < NEPS; e++) pref[e] = g_pref[e];

    unsigned lane = (unsigned)(tid & 31);
    for (unsigned idx = blockIdx.x * 256u + tid; idx < (unsigned)NN;
         idx += gridDim.x * 256u) {
        unsigned i = idx >> 12, j = idx & 4095u;
        float dv = g_d[idx];
        unsigned bits = __float_as_uint(dv);
        unsigned both = (unsigned)(g_vmb[i] & g_vmb[j]);
        bool pos = dv > 0.f;
        #pragma unroll
        for (int e = 0; e < NEPS; e++) {
            bool valid = pos && ((both >> e) & 1u);
            unsigned bin; bool cand;
            if (PASS == 0)      { cand = valid;                                bin = bits >> 20; }
            else if (PASS == 1) { cand = valid && ((bits >> 20) == pref[e]);   bin = (bits >> 9) & 2047u; }
            else                { cand = valid && ((bits >> 9)  == pref[e]);   bin = bits & 511u; }
            // warp-aggregated histogram add (bins are heavily skewed)
            unsigned key = cand ? bin : (0x80000000u | lane);
            unsigned peers = __match_any_sync(0xffffffffu, key);
            if (cand && lane == (unsigned)(__ffs(peers) - 1))
                atomicAdd(&sh[e * 2048 + bin], __popc(peers));
        }
    }
    __syncthreads();
    unsigned* gh = &g_hist[0][0];
    for (int q = tid; q < NEPS * 2048; q += 256) {
        unsigned v = sh[q];
        if (v) atomicAdd(&gh[q], v);
    }
}

__global__ void scan_kernel(int pass) {
    int tid = threadIdx.x;              // 128 threads: warp e handles eps e
    int e = tid >> 5, lane = tid & 31;

    unsigned chunkSum = 0;
    for (int q = 0; q < 64; q++) chunkSum += g_hist[e][lane * 64 + q];

    unsigned incl = chunkSum;
    #pragma unroll
    for (int o = 1; o < 32; o <<= 1) {
        unsigned v = __shfl_up_sync(0xffffffffu, incl, o);
        if (lane >= o) incl += v;
    }
    unsigned total = __shfl_sync(0xffffffffu, incl, 31);
    unsigned exclusive = incl - chunkSum;

    if (pass == 0 && lane == 0) {
        if (total == 0) {
            g_done[e] = 1;
            g_thrbits[e] = 0x7F800000u;   // +inf
            g_pref[e] = 0xFFFFFFFFu;      // impossible prefix
        } else {
            g_done[e] = 0;
        }
    }

    bool skip = (pass > 0) && (g_done[e] != 0);
    if (!skip && total > 0) {
        unsigned k = (pass == 0) ? ((total - 1u) >> 1) : g_k[e];
        bool mine = (exclusive <= k) && (k < exclusive + chunkSum);
        if (mine) {
            unsigned cum = exclusive, b = 0;
            for (int q = 0; q < 64; q++) {
                unsigned h = g_hist[e][lane * 64 + q];
                if (cum + h > k) { b = (unsigned)(lane * 64 + q); break; }
                cum += h;
            }
            g_k[e] = k - cum;
            if (pass == 0)      g_pref[e] = b;
            else if (pass == 1) g_pref[e] = (g_pref[e] << 11) | b;
            else                g_thrbits[e] = (g_pref[e] << 9) | b;
        }
    }
    __syncthreads();
    unsigned* gh = &g_hist[0][0];
    for (int q = tid; q < NEPS * 2048; q += 128) gh[q] = 0;
}

// ---------------- Stage 4: adjacency A + packed bitset ---------------------
__global__ void a_kernel(float* __restrict__ out) {
    unsigned gt   = blockIdx.x * 256u + threadIdx.x;
    unsigned gw   = gt >> 5;
    unsigned lane = gt & 31u;
    unsigned e    = gw >> 19;            // 4096*128 = 2^19 warps per eps
    unsigned rem  = gw & 0x7FFFFu;
    unsigned i    = rem >> 7;
    unsigned wc   = rem & 127u;
    unsigned j    = (wc << 5) + lane;

    float dv  = g_d[i * NPTS + j];
    float thr = __uint_as_float(g_thrbits[e]);
    unsigned both = (unsigned)(g_vmb[i] & g_vmb[j]);
    bool a = (dv <= thr) && ((both >> e) & 1u) && (i != j);

    out[A_OFF + e * 16777216u + i * 4096u + j] = a ? 1.f : 0.f;
    unsigned word = __ballot_sync(0xffffffffu, a);
    if (lane == 0) g_abits[e][(i << 7) + wc] = word;
}

// ---------------- Stage 5: tri = (A@A) * A via bitset popcount -------------
__global__ void __launch_bounds__(256)
tri_kernel(float* __restrict__ out) {
    int bx = blockIdx.x, by = blockIdx.y, e = blockIdx.z;
    if (by > bx) return;                 // symmetric: upper tiles only
    int i0 = by * 64, j0 = bx * 64;

    __shared__ __align__(16) unsigned char smraw[64 * 33 * 4 * 2];
    unsigned* shI = (unsigned*)smraw;
    unsigned* shJ = shI + 64 * 33;
    float* stage  = (float*)smraw;       // reused after compute loop

    int tx = threadIdx.x, ty = threadIdx.y;
    int tid = ty * 16 + tx;
    int acc[4][4] = {};
    const unsigned* __restrict__ Ab = g_abits[e];

    for (int kc = 0; kc < 4; kc++) {
        #pragma unroll
        for (int r = 0; r < 8; r++) {
            int lin = tid + r * 256;
            int row = lin >> 5, w = lin & 31;
            shI[row * 33 + w] = Ab[(i0 + row) * NWRD + kc * 32 + w];
            shJ[row * 33 + w] = Ab[(j0 + row) * NWRD + kc * 32 + w];
        }
        __syncthreads();
        #pragma unroll
        for (int w = 0; w < 32; w++) {
            unsigned ai[4], bj[4];
            #pragma unroll
            for (int a = 0; a < 4; a++) ai[a] = shI[(ty * 4 + a) * 33 + w];
            #pragma unroll
            for (int b = 0; b < 4; b++) bj[b] = shJ[(tx * 4 + b) * 33 + w];
            #pragma unroll
            for (int a = 0; a < 4; a++)
                #pragma unroll
                for (int b = 0; b < 4; b++)
                    acc[a][b] += __popc(ai[a] & bj[b]);
        }
        __syncthreads();
    }

    float vals[4][4];
    unsigned wIdx = (unsigned)(j0 + tx * 4) >> 5;   // same word for b=0..3
    #pragma unroll
    for (int a = 0; a < 4; a++) {
        int i = i0 + ty * 4 + a;
        unsigned word = Ab[i * NWRD + wIdx];
        #pragma unroll
        for (int b = 0; b < 4; b++) {
            int jb = (j0 + tx * 4 + b) & 31;
            vals[a][b] = ((word >> jb) & 1u) ? (float)acc[a][b] : 0.f;
        }
        *(float4*)&out[TRI_OFF + (unsigned)e * 16777216u +
                       (unsigned)i * 4096u + j0 + tx * 4] =
            make_float4(vals[a][0], vals[a][1], vals[a][2], vals[a][3]);
    }

    if (bx != by) {                      // write transposed tile (staged)
        __syncthreads();
        #pragma unroll
        for (int a = 0; a < 4; a++)
            #pragma unroll
            for (int b = 0; b < 4; b++)
                stage[(ty * 4 + a) * 65 + tx * 4 + b] = vals[a][b];
        __syncthreads();
        #pragma unroll
        for (int a = 0; a < 4; a++) {
            int jl = ty * 4 + a;
            float4 o;
            o.x = stage[(tx * 4 + 0) * 65 + jl];
            o.y = stage[(tx * 4 + 1) * 65 + jl];
            o.z = stage[(tx * 4 + 2) * 65 + jl];
            o.w = stage[(tx * 4 + 3) * 65 + jl];
            *(float4*)&out[TRI_OFF + (unsigned)e * 16777216u +
                           (unsigned)(j0 + jl) * 4096u + i0 + tx * 4] = o;
        }
    }
}

// ---------------- launch ---------------------------------------------------
extern "C" void kernel_launch(void* const* d_in, const int* in_sizes, int n_in,
                              void* d_out, int out_size) {
    const float* residue    = (const float*)d_in[0];
    const float* constraint = (const float*)d_in[1];
    const float* eps        = (const float*)d_in[2];
    float* out = (float*)d_out;

    prep_kernel<<<512, 256>>>(residue, constraint, eps, out);   // warp per row

    dim3 gGrid(64, 64), gBlk(16, 16);
    dist_kernel<<<gGrid, gBlk>>>(constraint);

    hist_kernel<0><<<2048, 256>>>(); scan_kernel<<<1, 128>>>(0);
    hist_kernel<1><<<2048, 256>>>(); scan_kernel<<<1, 128>>>(1);
    hist_kernel<2><<<2048, 256>>>(); scan_kernel<<<1, 128>>>(2);

    a_kernel<<<262144, 256>>>(out);

    dim3 tGrid(64, 64, NEPS);
    tri_kernel<<<tGrid, gBlk>>>(out);
}

// round 4
// speedup vs baseline: 1.0008x; 1.0008x over previous
#include <cuda_runtime.h>

// Problem constants
#define NPTS 4096
#define DIMK 256
#define NEPS 4
#define NWRD 128              // 4096 bits / 32 per row
#define NN   (NPTS*NPTS)      // 16777216

// Output layout (float32, concatenated in reference return order)
#define LOSS_OFF 0u
#define VM_OFF   4096u
#define A_OFF    20480u                      // 4096 + 4*4096
#define TRI_OFF  (20480u + 67108864u)        // + E*N*N

// ---------------- device scratch (globals: allocation-free rule) ----------
__device__ float         g_d[NN];                 // 67 MB distance matrix
__device__ unsigned      g_abits[NEPS][NPTS*NWRD];// 8 MB packed adjacency
__device__ float         g_sq[NPTS];
__device__ unsigned char g_vmb[NPTS];             // 4 mask bits per point
__device__ unsigned      g_hist[NEPS][2048];      // radix-select histograms
__device__ unsigned      g_pref[NEPS];
__device__ unsigned      g_k[NEPS];
__device__ unsigned      g_thrbits[NEPS];
__device__ int           g_done[NEPS];

// ---------------- Stage 1: losses, vmask, sqnorms --------------------------
// Replicates the hypothesized XLA GPU row-reduction order bit-exactly:
// one warp per row; each lane FMA-accumulates 8 lane-strided elements
// (stride 32, ascending), then a shfl_down tree (16,8,4,2,1).
__global__ void prep_kernel(const float* __restrict__ residue,
                            const float* __restrict__ constraint,
                            const float* __restrict__ eps,
                            float* __restrict__ out) {
    int gw   = (blockIdx.x * blockDim.x + threadIdx.x) >> 5;   // row id
    int lane = threadIdx.x & 31;
    if (gw >= NPTS) return;

    const float* __restrict__ c = constraint + (unsigned)gw * DIMK;
    const float* __restrict__ r = residue    + (unsigned)gw * DIMK;

    float s_sq = 0.f, s_ls = 0.f;
    #pragma unroll
    for (int j = 0; j < 8; j++) {
        float cv = c[lane + 32 * j];
        float rv = r[lane + 32 * j];
        s_sq = __fmaf_rn(cv, cv, s_sq);
        float df = __fadd_rn(rv, -cv);          // exact-rounded subtraction
        s_ls = __fmaf_rn(df, df, s_ls);
    }
    #pragma unroll
    for (int o = 16; o > 0; o >>= 1) {
        s_sq = __fadd_rn(s_sq, __shfl_down_sync(0xffffffffu, s_sq, o));
        s_ls = __fadd_rn(s_ls, __shfl_down_sync(0xffffffffu, s_ls, o));
    }

    if (lane == 0) {
        g_sq[gw] = s_sq;
        float loss = __fsqrt_rn(s_ls);
        out[LOSS_OFF + gw] = loss;
        unsigned char mb = 0;
        #pragma unroll
        for (int e = 0; e < NEPS; e++) {
            bool m = loss <= eps[e];
            mb |= (unsigned char)((m ? 1 : 0) << e);
            out[VM_OFF + (unsigned)e * NPTS + gw] = m ? 1.f : 0.f;
        }
        g_vmb[gw] = mb;
    }
}

// ---------------- Stage 2: pairwise distances (fp32 SGEMM) ----------------
// Strict ascending-k FMA chain per output element (cuBLAS SGEMM order).
// Epilogue replicates ((sq_i + sq_j) - 2*G) with exact-rounded ops.
// Diagonal computed NATURALLY (no zeroing): tiny positive d[i,i] values
// must enter the median's valid set exactly as in the reference.
__global__ void __launch_bounds__(256)
dist_kernel(const float* __restrict__ C) {
    __shared__ float shI[32 * 65];
    __shared__ float shJ[32 * 65];
    int bi = blockIdx.y, bj = blockIdx.x;
    int i0 = bi * 64, j0 = bj * 64;
    int tx = threadIdx.x, ty = threadIdx.y;
    int tid = ty * 16 + tx;
    float acc[4][4] = {};

    for (int k0 = 0; k0 < DIMK; k0 += 32) {
        #pragma unroll
        for (int r = 0; r < 2; r++) {
            int q   = tid + r * 256;
            int row = q >> 3;          // 8 float4 per 32-wide row
            int kq  = q & 7;
            float4 vI = *(const float4*)&C[(i0 + row) * DIMK + k0 + kq * 4];
            float4 vJ = *(const float4*)&C[(j0 + row) * DIMK + k0 + kq * 4];
            int b = kq * 4;
            shI[(b + 0) * 65 + row] = vI.x; shI[(b + 1) * 65 + row] = vI.y;
            shI[(b + 2) * 65 + row] = vI.z; shI[(b + 3) * 65 + row] = vI.w;
            shJ[(b + 0) * 65 + row] = vJ.x; shJ[(b + 1) * 65 + row] = vJ.y;
            shJ[(b + 2) * 65 + row] = vJ.z; shJ[(b + 3) * 65 + row] = vJ.w;
        }
        __syncthreads();
        #pragma unroll
        for (int kk = 0; kk < 32; kk++) {
            float ai[4], bb[4];
            #pragma unroll
            for (int a = 0; a < 4; a++) ai[a] = shI[kk * 65 + ty * 4 + a];
            #pragma unroll
            for (int b = 0; b < 4; b++) bb[b] = shJ[kk * 65 + tx * 4 + b];
            #pragma unroll
            for (int a = 0; a < 4; a++)
                #pragma unroll
                for (int b = 0; b < 4; b++)
                    acc[a][b] = __fmaf_rn(ai[a], bb[b], acc[a][b]);
        }
        __syncthreads();
    }

    float sqi[4], sqj[4];
    #pragma unroll
    for (int a = 0; a < 4; a++) sqi[a] = g_sq[i0 + ty * 4 + a];
    #pragma unroll
    for (int b = 0; b < 4; b++) sqj[b] = g_sq[j0 + tx * 4 + b];

    #pragma unroll
    for (int a = 0; a < 4; a++) {
        int i = i0 + ty * 4 + a;
        float v[4];
        #pragma unroll
        for (int b = 0; b < 4; b++) {
            float t1 = __fadd_rn(sqi[a], sqj[b]);              // sq_i + sq_j
            float g2 = __fmul_rn(2.0f, acc[a][b]);             // 2*G (exact)
            float d2 = __fadd_rn(t1, -g2);                     // rounded sub
            v[b] = __fsqrt_rn(fmaxf(d2, 0.0f));
        }
        *(float4*)&g_d[(unsigned)i * NPTS + j0 + tx * 4] =
            make_float4(v[0], v[1], v[2], v[3]);
    }
}

// ---------------- Stage 3: radix select of the lower median ---------------
template<int PASS>
__global__ void hist_kernel() {
    __shared__ unsigned sh[NEPS * 2048];
    int tid = threadIdx.x;
    for (int q = tid; q < NEPS * 2048; q += 256) sh[q] = 0;
    __syncthreads();

    unsigned pref[NEPS];
    #pragma unroll
    for (int e = 0; e < NEPS; e++) pref[e] = g_pref[e];

    unsigned lane = (unsigned)(tid & 31);
    for (unsigned idx = blockIdx.x * 256u + tid; idx < (unsigned)NN;
         idx += gridDim.x * 256u) {
        unsigned i = idx >> 12, j = idx & 4095u;
        float dv = g_d[idx];
        unsigned bits = __float_as_uint(dv);
        unsigned both = (unsigned)(g_vmb[i] & g_vmb[j]);
        bool pos = dv > 0.f;
        #pragma unroll
        for (int e = 0; e < NEPS; e++) {
            bool valid = pos && ((both >> e) & 1u);
            unsigned bin; bool cand;
            if (PASS == 0)      { cand = valid;                                bin = bits >> 20; }
            else if (PASS == 1) { cand = valid && ((bits >> 20) == pref[e]);   bin = (bits >> 9) & 2047u; }
            else                { cand = valid && ((bits >> 9)  == pref[e]);   bin = bits & 511u; }
            // warp-aggregated histogram add (bins are heavily skewed)
            unsigned key = cand ? bin : (0x80000000u | lane);
            unsigned peers = __match_any_sync(0xffffffffu, key);
            if (cand && lane == (unsigned)(__ffs(peers) - 1))
                atomicAdd(&sh[e * 2048 + bin], __popc(peers));
        }
    }
    __syncthreads();
    unsigned* gh = &g_hist[0][0];
    for (int q = tid; q < NEPS * 2048; q += 256) {
        unsigned v = sh[q];
        if (v) atomicAdd(&gh[q], v);
    }
}

__global__ void scan_kernel(int pass) {
    int tid = threadIdx.x;              // 128 threads: warp e handles eps e
    int e = tid >> 5, lane = tid & 31;

    unsigned chunkSum = 0;
    for (int q = 0; q < 64; q++) chunkSum += g_hist[e][lane * 64 + q];

    unsigned incl = chunkSum;
    #pragma unroll
    for (int o = 1; o < 32; o <<= 1) {
        unsigned v = __shfl_up_sync(0xffffffffu, incl, o);
        if (lane >= o) incl += v;
    }
    unsigned total = __shfl_sync(0xffffffffu, incl, 31);
    unsigned exclusive = incl - chunkSum;

    if (pass == 0 && lane == 0) {
        if (total == 0) {
            g_done[e] = 1;
            g_thrbits[e] = 0x7F800000u;   // +inf
            g_pref[e] = 0xFFFFFFFFu;      // impossible prefix
        } else {
            g_done[e] = 0;
        }
    }

    bool skip = (pass > 0) && (g_done[e] != 0);
    if (!skip && total > 0) {
        unsigned k = (pass == 0) ? ((total - 1u) >> 1) : g_k[e];
        bool mine = (exclusive <= k) && (k < exclusive + chunkSum);
        if (mine) {
            unsigned cum = exclusive, b = 0;
            for (int q = 0; q < 64; q++) {
                unsigned h = g_hist[e][lane * 64 + q];
                if (cum + h > k) { b = (unsigned)(lane * 64 + q); break; }
                cum += h;
            }
            g_k[e] = k - cum;
            if (pass == 0)      g_pref[e] = b;
            else if (pass == 1) g_pref[e] = (g_pref[e] << 11) | b;
            else                g_thrbits[e] = (g_pref[e] << 9) | b;
        }
    }
    __syncthreads();
    unsigned* gh = &g_hist[0][0];
    for (int q = tid; q < NEPS * 2048; q += 128) gh[q] = 0;
}

// ---------------- Stage 4: adjacency A + packed bitset ---------------------
__global__ void a_kernel(float* __restrict__ out) {
    unsigned gt   = blockIdx.x * 256u + threadIdx.x;
    unsigned gw   = gt >> 5;
    unsigned lane = gt & 31u;
    unsigned e    = gw >> 19;            // 4096*128 = 2^19 warps per eps
    unsigned rem  = gw & 0x7FFFFu;
    unsigned i    = rem >> 7;
    unsigned wc   = rem & 127u;
    unsigned j    = (wc << 5) + lane;

    float dv  = g_d[i * NPTS + j];
    float thr = __uint_as_float(g_thrbits[e]);
    unsigned both = (unsigned)(g_vmb[i] & g_vmb[j]);
    bool a = (dv <= thr) && ((both >> e) & 1u) && (i != j);

    out[A_OFF + e * 16777216u + i * 4096u + j] = a ? 1.f : 0.f;
    unsigned word = __ballot_sync(0xffffffffu, a);
    if (lane == 0) g_abits[e][(i << 7) + wc] = word;
}

// ---------------- Stage 5: tri = (A@A) * A via bitset popcount -------------
__global__ void __launch_bounds__(256)
tri_kernel(float* __restrict__ out) {
    int bx = blockIdx.x, by = blockIdx.y, e = blockIdx.z;
    if (by > bx) return;                 // symmetric: upper tiles only
    int i0 = by * 64, j0 = bx * 64;

    __shared__ __align__(16) unsigned char smraw[64 * 33 * 4 * 2];
    unsigned* shI = (unsigned*)smraw;
    unsigned* shJ = shI + 64 * 33;
    float* stage  = (float*)smraw;       // reused after compute loop

    int tx = threadIdx.x, ty = threadIdx.y;
    int tid = ty * 16 + tx;
    int acc[4][4] = {};
    const unsigned* __restrict__ Ab = g_abits[e];

    for (int kc = 0; kc < 4; kc++) {
        #pragma unroll
        for (int r = 0; r < 8; r++) {
            int lin = tid + r * 256;
            int row = lin >> 5, w = lin & 31;
            shI[row * 33 + w] = Ab[(i0 + row) * NWRD + kc * 32 + w];
            shJ[row * 33 + w] = Ab[(j0 + row) * NWRD + kc * 32 + w];
        }
        __syncthreads();
        #pragma unroll
        for (int w = 0; w < 32; w++) {
            unsigned ai[4], bj[4];
            #pragma unroll
            for (int a = 0; a < 4; a++) ai[a] = shI[(ty * 4 + a) * 33 + w];
            #pragma unroll
            for (int b = 0; b < 4; b++) bj[b] = shJ[(tx * 4 + b) * 33 + w];
            #pragma unroll
            for (int a = 0; a < 4; a++)
                #pragma unroll
                for (int b = 0; b < 4; b++)
                    acc[a][b] += __popc(ai[a] & bj[b]);
        }
        __syncthreads();
    }

    float vals[4][4];
    unsigned wIdx = (unsigned)(j0 + tx * 4) >> 5;   // same word for b=0..3
    #pragma unroll
    for (int a = 0; a < 4; a++) {
        int i = i0 + ty * 4 + a;
        unsigned word = Ab[i * NWRD + wIdx];
        #pragma unroll
        for (int b = 0; b < 4; b++) {
            int jb = (j0 + tx * 4 + b) & 31;
            vals[a][b] = ((word >> jb) & 1u) ? (float)acc[a][b] : 0.f;
        }
        *(float4*)&out[TRI_OFF + (unsigned)e * 16777216u +
                       (unsigned)i * 4096u + j0 + tx * 4] =
            make_float4(vals[a][0], vals[a][1], vals[a][2], vals[a][3]);
    }

    if (bx != by) {                      // write transposed tile (staged)
        __syncthreads();
        #pragma unroll
        for (int a = 0; a < 4; a++)
            #pragma unroll
            for (int b = 0; b < 4; b++)
                stage[(ty * 4 + a) * 65 + tx * 4 + b] = vals[a][b];
        __syncthreads();
        #pragma unroll
        for (int a = 0; a < 4; a++) {
            int jl = ty * 4 + a;
            float4 o;
            o.x = stage[(tx * 4 + 0) * 65 + jl];
            o.y = stage[(tx * 4 + 1) * 65 + jl];
            o.z = stage[(tx * 4 + 2) * 65 + jl];
            o.w = stage[(tx * 4 + 3) * 65 + jl];
            *(float4*)&out[TRI_OFF + (unsigned)e * 16777216u +
                           (unsigned)(j0 + jl) * 4096u + i0 + tx * 4] = o;
        }
    }
}

// ---------------- launch ---------------------------------------------------
extern "C" void kernel_launch(void* const* d_in, const int* in_sizes, int n_in,
                              void* d_out, int out_size) {
    const float* residue    = (const float*)d_in[0];
    const float* constraint = (const float*)d_in[1];
    const float* eps        = (const float*)d_in[2];
    float* out = (float*)d_out;

    prep_kernel<<<512, 256>>>(residue, constraint, eps, out);   // warp per row

    dim3 gGrid(64, 64), gBlk(16, 16);
    dist_kernel<<<gGrid, gBlk>>>(constraint);

    hist_kernel<0><<<2048, 256>>>(); scan_kernel<<<1, 128>>>(0);
    hist_kernel<1><<<2048, 256>>>(); scan_kernel<<<1, 128>>>(1);
    hist_kernel<2><<<2048, 256>>>(); scan_kernel<<<1, 128>>>(2);

    a_kernel<<<262144, 256>>>(out);

    dim3 tGrid(64, 64, NEPS);
    tri_kernel<<<tGrid, gBlk>>>(out);
}

// round 7
// speedup vs baseline: 1.0495x; 1.0487x over previous
#include <cuda_runtime.h>

// Problem constants
#define NPTS 4096
#define DIMK 256
#define NEPS 4
#define NWRD 128              // 4096 bits / 32 per row
#define NN   (NPTS*NPTS)      // 16777216

// Output layout (float32, concatenated in reference return order)
#define LOSS_OFF 0u
#define VM_OFF   4096u
#define A_OFF    20480u                      // 4096 + 4*4096
#define TRI_OFF  (20480u + 67108864u)        // + E*N*N

// ---------------- device scratch (globals: allocation-free rule) ----------
__device__ float         g_d[NN];                 // 67 MB distance matrix
__device__ unsigned      g_abits[NEPS][NPTS*NWRD];// 8 MB packed adjacency
__device__ float         g_sq[NPTS];
__device__ unsigned char g_vmb[NPTS];             // 4 mask bits per point
__device__ unsigned      g_hist[NEPS][2048];      // radix-select histograms
__device__ unsigned      g_pref[NEPS];
__device__ unsigned      g_k[NEPS];
__device__ unsigned      g_thrbits[NEPS];
__device__ int           g_done[NEPS];

// ---------------- Stage 1: losses, vmask, sqnorms --------------------------
// Bit-exact XLA row-reduce: warp per row, lane-stride-32 ascending FMA, then
// shfl_down tree (16,8,4,2,1). DO NOT change the arithmetic order.
__global__ void prep_kernel(const float* __restrict__ residue,
                            const float* __restrict__ constraint,
                            const float* __restrict__ eps,
                            float* __restrict__ out) {
    int gw   = (blockIdx.x * blockDim.x + threadIdx.x) >> 5;   // row id
    int lane = threadIdx.x & 31;
    if (gw >= NPTS) return;

    const float* __restrict__ c = constraint + (unsigned)gw * DIMK;
    const float* __restrict__ r = residue    + (unsigned)gw * DIMK;

    float s_sq = 0.f, s_ls = 0.f;
    #pragma unroll
    for (int j = 0; j < 8; j++) {
        float cv = c[lane + 32 * j];
        float rv = r[lane + 32 * j];
        s_sq = __fmaf_rn(cv, cv, s_sq);
        float df = __fadd_rn(rv, -cv);
        s_ls = __fmaf_rn(df, df, s_ls);
    }
    #pragma unroll
    for (int o = 16; o > 0; o >>= 1) {
        s_sq = __fadd_rn(s_sq, __shfl_down_sync(0xffffffffu, s_sq, o));
        s_ls = __fadd_rn(s_ls, __shfl_down_sync(0xffffffffu, s_ls, o));
    }

    if (lane == 0) {
        g_sq[gw] = s_sq;
        float loss = __fsqrt_rn(s_ls);
        out[LOSS_OFF + gw] = loss;
        unsigned char mb = 0;
        #pragma unroll
        for (int e = 0; e < NEPS; e++) {
            bool m = loss <= eps[e];
            mb |= (unsigned char)((m ? 1 : 0) << e);
            out[VM_OFF + (unsigned)e * NPTS + gw] = m ? 1.f : 0.f;
        }
        g_vmb[gw] = mb;
    }
}

// ---------------- Stage 2: pairwise distances (fp32 SGEMM) ----------------
// 128x128 tile, 8x8 per thread (strided row/col mapping: ty+16a / tx+16b).
// Per-element accumulation chain: single accumulator, k strictly ascending
// -> bit-identical to the round-4 passing kernel. Diagonal natural.
__global__ void __launch_bounds__(256, 2)
dist_kernel(const float* __restrict__ C) {
    __shared__ float shI[16 * 132];
    __shared__ float shJ[16 * 132];
    int i0 = blockIdx.y * 128, j0 = blockIdx.x * 128;
    int t  = threadIdx.x;
    int tx = t & 15, ty = t >> 4;
    float acc[8][8] = {};

    for (int k0 = 0; k0 < DIMK; k0 += 16) {
        #pragma unroll
        for (int r = 0; r < 2; r++) {
            int q   = t + r * 256;        // 0..511
            int row = q & 127;
            int kv  = q >> 7;             // 0..3 -> k offset kv*4
            float4 vI = *(const float4*)&C[(i0 + row) * DIMK + k0 + kv * 4];
            float4 vJ = *(const float4*)&C[(j0 + row) * DIMK + k0 + kv * 4];
            shI[(kv * 4 + 0) * 132 + row] = vI.x;
            shI[(kv * 4 + 1) * 132 + row] = vI.y;
            shI[(kv * 4 + 2) * 132 + row] = vI.z;
            shI[(kv * 4 + 3) * 132 + row] = vI.w;
            shJ[(kv * 4 + 0) * 132 + row] = vJ.x;
            shJ[(kv * 4 + 1) * 132 + row] = vJ.y;
            shJ[(kv * 4 + 2) * 132 + row] = vJ.z;
            shJ[(kv * 4 + 3) * 132 + row] = vJ.w;
        }
        __syncthreads();
        #pragma unroll
        for (int kk = 0; kk < 16; kk++) {
            float ai[8], bj[8];
            #pragma unroll
            for (int a = 0; a < 8; a++) ai[a] = shI[kk * 132 + ty + 16 * a];
            #pragma unroll
            for (int b = 0; b < 8; b++) bj[b] = shJ[kk * 132 + tx + 16 * b];
            #pragma unroll
            for (int a = 0; a < 8; a++)
                #pragma unroll
                for (int b = 0; b < 8; b++)
                    acc[a][b] = __fmaf_rn(ai[a], bj[b], acc[a][b]);
        }
        __syncthreads();
    }

    float sqi[8], sqj[8];
    #pragma unroll
    for (int a = 0; a < 8; a++) sqi[a] = g_sq[i0 + ty + 16 * a];
    #pragma unroll
    for (int b = 0; b < 8; b++) sqj[b] = g_sq[j0 + tx + 16 * b];

    #pragma unroll
    for (int a = 0; a < 8; a++) {
        int i = i0 + ty + 16 * a;
        #pragma unroll
        for (int b = 0; b < 8; b++) {
            float t1 = __fadd_rn(sqi[a], sqj[b]);
            float g2 = __fmul_rn(2.0f, acc[a][b]);
            float d2 = __fadd_rn(t1, -g2);
            g_d[(unsigned)i * NPTS + j0 + tx + 16 * b] =
                __fsqrt_rn(fmaxf(d2, 0.0f));
        }
    }
}

// ---------------- Stage 3: radix select of the lower median ---------------
template<int PASS>
__global__ void hist_kernel() {
    __shared__ unsigned sh[NEPS * 2048];
    int tid = threadIdx.x;
    for (int q = tid; q < NEPS * 2048; q += 256) sh[q] = 0;
    __syncthreads();

    unsigned pref[NEPS];
    #pragma unroll
    for (int e = 0; e < NEPS; e++) pref[e] = g_pref[e];

    unsigned lane = (unsigned)(tid & 31);
    for (unsigned idx = blockIdx.x * 256u + tid; idx < (unsigned)NN;
         idx += gridDim.x * 256u) {
        unsigned i = idx >> 12, j = idx & 4095u;
        float dv = g_d[idx];
        unsigned bits = __float_as_uint(dv);
        unsigned both = (unsigned)(g_vmb[i] & g_vmb[j]);
        bool pos = dv > 0.f;
        #pragma unroll
        for (int e = 0; e < NEPS; e++) {
            bool valid = pos && ((both >> e) & 1u);
            unsigned bin; bool cand;
            if (PASS == 0)      { cand = valid;                                bin = bits >> 20; }
            else if (PASS == 1) { cand = valid && ((bits >> 20) == pref[e]);   bin = (bits >> 9) & 2047u; }
            else                { cand = valid && ((bits >> 9)  == pref[e]);   bin = bits & 511u; }
            unsigned key = cand ? bin : (0x80000000u | lane);
            unsigned peers = __match_any_sync(0xffffffffu, key);
            if (cand && lane == (unsigned)(__ffs(peers) - 1))
                atomicAdd(&sh[e * 2048 + bin], __popc(peers));
        }
    }
    __syncthreads();
    unsigned* gh = &g_hist[0][0];
    for (int q = tid; q < NEPS * 2048; q += 256) {
        unsigned v = sh[q];
        if (v) atomicAdd(&gh[q], v);
    }
}

__global__ void scan_kernel(int pass) {
    int tid = threadIdx.x;              // 128 threads: warp e handles eps e
    int e = tid >> 5, lane = tid & 31;

    unsigned chunkSum = 0;
    for (int q = 0; q < 64; q++) chunkSum += g_hist[e][lane * 64 + q];

    unsigned incl = chunkSum;
    #pragma unroll
    for (int o = 1; o < 32; o <<= 1) {
        unsigned v = __shfl_up_sync(0xffffffffu, incl, o);
        if (lane >= o) incl += v;
    }
    unsigned total = __shfl_sync(0xffffffffu, incl, 31);
    unsigned exclusive = incl - chunkSum;

    if (pass == 0 && lane == 0) {
        if (total == 0) {
            g_done[e] = 1;
            g_thrbits[e] = 0x7F800000u;   // +inf
            g_pref[e] = 0xFFFFFFFFu;      // impossible prefix
        } else {
            g_done[e] = 0;
        }
    }

    bool skip = (pass > 0) && (g_done[e] != 0);
    if (!skip && total > 0) {
        unsigned k = (pass == 0) ? ((total - 1u) >> 1) : g_k[e];
        bool mine = (exclusive <= k) && (k < exclusive + chunkSum);
        if (mine) {
            unsigned cum = exclusive, b = 0;
            for (int q = 0; q < 64; q++) {
                unsigned h = g_hist[e][lane * 64 + q];
                if (cum + h > k) { b = (unsigned)(lane * 64 + q); break; }
                cum += h;
            }
            g_k[e] = k - cum;
            if (pass == 0)      g_pref[e] = b;
            else if (pass == 1) g_pref[e] = (g_pref[e] << 11) | b;
            else                g_thrbits[e] = (g_pref[e] << 9) | b;
        }
    }
    __syncthreads();
    unsigned* gh = &g_hist[0][0];
    for (int q = tid; q < NEPS * 2048; q += 128) gh[q] = 0;
}

// ---------------- Stage 4: adjacency A + packed bitset (all eps, 1 d read) -
__global__ void a_kernel(float* __restrict__ out) {
    unsigned gw   = (blockIdx.x * 256u + threadIdx.x) >> 5;  // warp: (i, wc)
    unsigned lane = threadIdx.x & 31u;
    unsigned i    = gw >> 7;
    unsigned wc   = gw & 127u;
    unsigned j    = (wc << 5) + lane;

    float dv = g_d[i * NPTS + j];
    unsigned both = (unsigned)(g_vmb[i] & g_vmb[j]);
    bool offd = (i != j);

    #pragma unroll
    for (int e = 0; e < NEPS; e++) {
        float thr = __uint_as_float(g_thrbits[e]);
        bool a = (dv <= thr) && ((both >> e) & 1u) && offd;
        out[A_OFF + (unsigned)e * 16777216u + i * 4096u + j] = a ? 1.f : 0.f;
        unsigned word = __ballot_sync(0xffffffffu, a);
        if (lane == 0) g_abits[e][(i << 7) + wc] = word;
    }
}

// ---------------- Stage 5: tri = (A@A) * A via bitset popcount -------------
// 128x128 tiles, 8x8 per thread (strided mapping), uint2 shared loads.
// Symmetric: upper tiles only; transposed tile staged through smem halves.
__global__ void __launch_bounds__(256, 2)
tri_kernel(float* __restrict__ out) {
    int bx = blockIdx.x, by = blockIdx.y, e = blockIdx.z;
    if (by > bx) return;
    int i0 = by * 128, j0 = bx * 128;

    __shared__ __align__(16) unsigned char smraw[128 * 34 * 4 * 2]; // 34816 B
    unsigned* shI = (unsigned*)smraw;
    unsigned* shJ = shI + 128 * 34;
    float* stage  = (float*)smraw;         // 64*129 floats = 33024 B, reused
    __shared__ unsigned aMask[128 * 4];    // A bits of this tile (rows x 4 w)

    int t  = threadIdx.x;
    int tx = t & 15, ty = t >> 4;
    int acc[8][8] = {};
    const unsigned* __restrict__ Ab = g_abits[e];

    int wb    = bx * 4;          // first word index of this tile's columns
    int cstar = wb >> 5;         // k-chunk containing the tile's own columns
    int wo    = wb & 31;         // offset within that chunk (<= 28)

    for (int kc = 0; kc < 4; kc++) {
        // BUGFIX (round 6): tile is 128 rows x 32 words = 4096 words per
        // buffer -> 16 iterations of 256 threads, not 8 (which filled only
        // rows 0..63 and left rows 64..127 as stale garbage).
        #pragma unroll
        for (int r = 0; r < 16; r++) {
            int q = t + r * 256;              // 0..4095
            int row = q >> 5, w = q & 31;
            shI[row * 34 + w] = Ab[(i0 + row) * NWRD + kc * 32 + w];
        }
        #pragma unroll
        for (int r = 0; r < 16; r++) {
            int q = t + r * 256;
            int row = q >> 5, w = q & 31;
            shJ[row * 34 + w] = Ab[(j0 + row) * NWRD + kc * 32 + w];
        }
        __syncthreads();
        if (kc == cstar) {
            aMask[t]       = shI[(t >> 2) * 34 + wo + (t & 3)];
            aMask[t + 256] = shI[((t + 256) >> 2) * 34 + wo + ((t + 256) & 3)];
        }

        #pragma unroll 4
        for (int w2 = 0; w2 < 16; w2++) {
            uint2 ai[8], bj[8];
            #pragma unroll
            for (int a = 0; a < 8; a++)
                ai[a] = *(const uint2*)&shI[(ty + 16 * a) * 34 + 2 * w2];
            #pragma unroll
            for (int b = 0; b < 8; b++)
                bj[b] = *(const uint2*)&shJ[(tx + 16 * b) * 34 + 2 * w2];
            #pragma unroll
            for (int a = 0; a < 8; a++)
                #pragma unroll
                for (int b = 0; b < 8; b++)
                    acc[a][b] += __popc(ai[a].x & bj[b].x)
                               + __popc(ai[a].y & bj[b].y);
        }
        __syncthreads();
    }

    // normal-orientation write (masked by A)
    #pragma unroll
    for (int a = 0; a < 8; a++) {
        int il = ty + 16 * a;
        #pragma unroll
        for (int b = 0; b < 8; b++) {
            int jc = tx + 16 * b;
            unsigned word = aMask[il * 4 + (jc >> 5)];
            float v = ((word >> (jc & 31)) & 1u) ? (float)acc[a][b] : 0.f;
            out[TRI_OFF + (unsigned)e * 16777216u +
                (unsigned)(i0 + il) * 4096u + j0 + jc] = v;
        }
    }

    if (bx != by) {
        // transposed tile: stage 64 i-rows at a time through smem
        #pragma unroll
        for (int h = 0; h < 2; h++) {
            __syncthreads();
            #pragma unroll
            for (int a = h * 4; a < h * 4 + 4; a++) {
                int il = ty + 16 * a;
                int i64 = il - h * 64;               // 0..63
                #pragma unroll
                for (int b = 0; b < 8; b++) {
                    int jc = tx + 16 * b;
                    unsigned word = aMask[il * 4 + (jc >> 5)];
                    float v = ((word >> (jc & 31)) & 1u) ? (float)acc[a][b] : 0.f;
                    stage[i64 * 129 + jc] = v;
                }
            }
            __syncthreads();
            #pragma unroll
            for (int a = 0; a < 8; a++) {
                int jl = ty + 16 * a;                // output row within j-tile
                #pragma unroll
                for (int b = 0; b < 4; b++) {
                    int ic = tx + 16 * b;            // 0..63
                    float v = stage[ic * 129 + jl];
                    out[TRI_OFF + (unsigned)e * 16777216u +
                        (unsigned)(j0 + jl) * 4096u + i0 + h * 64 + ic] = v;
                }
            }
        }
    }
}

// ---------------- launch ---------------------------------------------------
extern "C" void kernel_launch(void* const* d_in, const int* in_sizes, int n_in,
                              void* d_out, int out_size) {
    const float* residue    = (const float*)d_in[0];
    const float* constraint = (const float*)d_in[1];
    const float* eps        = (const float*)d_in[2];
    float* out = (float*)d_out;

    prep_kernel<<<512, 256>>>(residue, constraint, eps, out);

    dim3 gGrid(32, 32);
    dist_kernel<<<gGrid, 256>>>(constraint);

    hist_kernel<0><<<2048, 256>>>(); scan_kernel<<<1, 128>>>(0);
    hist_kernel<1><<<2048, 256>>>(); scan_kernel<<<1, 128>>>(1);
    hist_kernel<2><<<2048, 256>>>(); scan_kernel<<<1, 128>>>(2);

    a_kernel<<<65536, 256>>>(out);

    dim3 tGrid(32, 32, NEPS);
    tri_kernel<<<tGrid, 256>>>(out);
}

// round 8
// speedup vs baseline: 2.1159x; 2.0160x over previous
#include <cuda_runtime.h>

// Problem constants
#define NPTS 4096
#define DIMK 256
#define NEPS 4
#define NWRD 128              // 4096 bits / 32 per row
#define NN   (NPTS*NPTS)      // 16777216

// Output layout (float32, concatenated in reference return order)
#define LOSS_OFF 0u
#define VM_OFF   4096u
#define A_OFF    20480u                      // 4096 + 4*4096
#define TRI_OFF  (20480u + 67108864u)        // + E*N*N

// ---------------- device scratch (globals: allocation-free rule) ----------
__device__ float         g_d[NN];                 // 67 MB distance matrix
__device__ unsigned      g_abits[NEPS][NPTS*NWRD];// 8 MB packed adjacency
__device__ unsigned      g_cbits[NEPS][NPTS*NWRD];// 8 MB compacted adjacency
__device__ float         g_tric[(size_t)NEPS*NN]; // 268 MB compacted counts
__device__ float         g_sq[NPTS];
__device__ unsigned char g_vmb[NPTS];             // 4 mask bits per point
__device__ int           g_rank[NEPS][NPTS];      // rank among alive, -1 dead
__device__ int           g_plist[NEPS][NPTS];     // rank -> point index
__device__ int           g_m[NEPS];               // alive count
__device__ unsigned      g_hist[NEPS][2048];      // radix-select histograms
__device__ unsigned      g_pref[NEPS];
__device__ unsigned      g_k[NEPS];
__device__ unsigned      g_thrbits[NEPS];
__device__ int           g_done[NEPS];

// ---------------- Stage 1: losses, vmask, sqnorms --------------------------
// Bit-exact XLA row-reduce: warp per row, lane-stride-32 ascending FMA, then
// shfl_down tree (16,8,4,2,1). DO NOT change the arithmetic order.
__global__ void prep_kernel(const float* __restrict__ residue,
                            const float* __restrict__ constraint,
                            const float* __restrict__ eps,
                            float* __restrict__ out) {
    int gw   = (blockIdx.x * blockDim.x + threadIdx.x) >> 5;   // row id
    int lane = threadIdx.x & 31;
    if (gw >= NPTS) return;

    const float* __restrict__ c = constraint + (unsigned)gw * DIMK;
    const float* __restrict__ r = residue    + (unsigned)gw * DIMK;

    float s_sq = 0.f, s_ls = 0.f;
    #pragma unroll
    for (int j = 0; j < 8; j++) {
        float cv = c[lane + 32 * j];
        float rv = r[lane + 32 * j];
        s_sq = __fmaf_rn(cv, cv, s_sq);
        float df = __fadd_rn(rv, -cv);
        s_ls = __fmaf_rn(df, df, s_ls);
    }
    #pragma unroll
    for (int o = 16; o > 0; o >>= 1) {
        s_sq = __fadd_rn(s_sq, __shfl_down_sync(0xffffffffu, s_sq, o));
        s_ls = __fadd_rn(s_ls, __shfl_down_sync(0xffffffffu, s_ls, o));
    }

    if (lane == 0) {
        g_sq[gw] = s_sq;
        float loss = __fsqrt_rn(s_ls);
        out[LOSS_OFF + gw] = loss;
        unsigned char mb = 0;
        #pragma unroll
        for (int e = 0; e < NEPS; e++) {
            bool m = loss <= eps[e];
            mb |= (unsigned char)((m ? 1 : 0) << e);
            out[VM_OFF + (unsigned)e * NPTS + gw] = m ? 1.f : 0.f;
        }
        g_vmb[gw] = mb;
    }
}

// ---------------- Stage 1b: per-eps compaction ranks ------------------------
// 128 threads; warp e handles eps e. Lane covers 128 consecutive entries.
__global__ void ranks_kernel() {
    int e = threadIdx.x >> 5, lane = threadIdx.x & 31;
    int base = lane * 128;
    int cnt = 0;
    for (int q = 0; q < 128; q++)
        cnt += (g_vmb[base + q] >> e) & 1;
    int incl = cnt;
    #pragma unroll
    for (int o = 1; o < 32; o <<= 1) {
        int v = __shfl_up_sync(0xffffffffu, incl, o);
        if (lane >= o) incl += v;
    }
    int m = __shfl_sync(0xffffffffu, incl, 31);
    int run = incl - cnt;
    for (int q = 0; q < 128; q++) {
        int idx = base + q;
        if ((g_vmb[idx] >> e) & 1) {
            g_rank[e][idx] = run;
            g_plist[e][run] = idx;
            run++;
        } else {
            g_rank[e][idx] = -1;
        }
    }
    if (lane == 0) g_m[e] = m;
}

// ---------------- Stage 2: pairwise distances (fp32 SGEMM) ----------------
// FROZEN arithmetic: single accumulator, k strictly ascending.
__global__ void __launch_bounds__(256, 2)
dist_kernel(const float* __restrict__ C) {
    __shared__ float shI[16 * 132];
    __shared__ float shJ[16 * 132];
    int i0 = blockIdx.y * 128, j0 = blockIdx.x * 128;
    int t  = threadIdx.x;
    int tx = t & 15, ty = t >> 4;
    float acc[8][8] = {};

    for (int k0 = 0; k0 < DIMK; k0 += 16) {
        #pragma unroll
        for (int r = 0; r < 2; r++) {
            int q   = t + r * 256;        // 0..511
            int row = q & 127;
            int kv  = q >> 7;             // 0..3 -> k offset kv*4
            float4 vI = *(const float4*)&C[(i0 + row) * DIMK + k0 + kv * 4];
            float4 vJ = *(const float4*)&C[(j0 + row) * DIMK + k0 + kv * 4];
            shI[(kv * 4 + 0) * 132 + row] = vI.x;
            shI[(kv * 4 + 1) * 132 + row] = vI.y;
            shI[(kv * 4 + 2) * 132 + row] = vI.z;
            shI[(kv * 4 + 3) * 132 + row] = vI.w;
            shJ[(kv * 4 + 0) * 132 + row] = vJ.x;
            shJ[(kv * 4 + 1) * 132 + row] = vJ.y;
            shJ[(kv * 4 + 2) * 132 + row] = vJ.z;
            shJ[(kv * 4 + 3) * 132 + row] = vJ.w;
        }
        __syncthreads();
        #pragma unroll
        for (int kk = 0; kk < 16; kk++) {
            float ai[8], bj[8];
            #pragma unroll
            for (int a = 0; a < 8; a++) ai[a] = shI[kk * 132 + ty + 16 * a];
            #pragma unroll
            for (int b = 0; b < 8; b++) bj[b] = shJ[kk * 132 + tx + 16 * b];
            #pragma unroll
            for (int a = 0; a < 8; a++)
                #pragma unroll
                for (int b = 0; b < 8; b++)
                    acc[a][b] = __fmaf_rn(ai[a], bj[b], acc[a][b]);
        }
        __syncthreads();
    }

    float sqi[8], sqj[8];
    #pragma unroll
    for (int a = 0; a < 8; a++) sqi[a] = g_sq[i0 + ty + 16 * a];
    #pragma unroll
    for (int b = 0; b < 8; b++) sqj[b] = g_sq[j0 + tx + 16 * b];

    #pragma unroll
    for (int a = 0; a < 8; a++) {
        int i = i0 + ty + 16 * a;
        #pragma unroll
        for (int b = 0; b < 8; b++) {
            float t1 = __fadd_rn(sqi[a], sqj[b]);
            float g2 = __fmul_rn(2.0f, acc[a][b]);
            float d2 = __fadd_rn(t1, -g2);
            g_d[(unsigned)i * NPTS + j0 + tx + 16 * b] =
                __fsqrt_rn(fmaxf(d2, 0.0f));
        }
    }
}

// ---------------- pad/zero kernels (also make hist0 land at launch #6) -----
__global__ void hzero_kernel(int half) {
    int q = blockIdx.x * 256 + threadIdx.x + half * 4096;
    if (q < NEPS * 2048) ((unsigned*)g_hist)[q] = 0u;
}

// ---------------- Stage 3: radix select of the lower median ---------------
// float4-vectorized; count-weighted warp-aggregated shared atomics.
template<int PASS>
__global__ void hist_kernel() {
    __shared__ unsigned sh[NEPS * 2048];
    int tid = threadIdx.x;
    for (int q = tid; q < NEPS * 2048; q += 256) sh[q] = 0;
    __syncthreads();

    unsigned pref[NEPS];
    #pragma unroll
    for (int e = 0; e < NEPS; e++) pref[e] = g_pref[e];

    unsigned lane = (unsigned)(tid & 31);
    const float4* __restrict__ d4 = (const float4*)g_d;
    for (unsigned idx = blockIdx.x * 256u + tid; idx < (unsigned)(NN / 4);
         idx += gridDim.x * 256u) {
        float4 v = d4[idx];
        unsigned i  = idx >> 10;
        unsigned j4 = (idx & 1023u) * 4u;
        uchar4 vb = *(const uchar4*)&g_vmb[j4];
        unsigned mi_ = (unsigned)g_vmb[i];
        float dv[4] = {v.x, v.y, v.z, v.w};
        unsigned both[4] = {mi_ & vb.x, mi_ & vb.y, mi_ & vb.z, mi_ & vb.w};
        unsigned bitsv[4];
        bool pos[4];
        #pragma unroll
        for (int c = 0; c < 4; c++) {
            bitsv[c] = __float_as_uint(dv[c]);
            pos[c]   = dv[c] > 0.f;
        }
        #pragma unroll
        for (int e = 0; e < NEPS; e++) {
            // per-lane merged (bin, count) list over the 4 elements
            unsigned mb[4]; int mc[4]; int nm = 0;
            #pragma unroll
            for (int c = 0; c < 4; c++) {
                bool valid = pos[c] && ((both[c] >> e) & 1u);
                unsigned bin; bool cand;
                if (PASS == 0)      { cand = valid;                                    bin = bitsv[c] >> 20; }
                else if (PASS == 1) { cand = valid && ((bitsv[c] >> 20) == pref[e]);   bin = (bitsv[c] >> 9) & 2047u; }
                else                { cand = valid && ((bitsv[c] >> 9)  == pref[e]);   bin = bitsv[c] & 511u; }
                if (cand) {
                    bool found = false;
                    for (int q = 0; q < nm; q++)
                        if (mb[q] == bin) { mc[q]++; found = true; break; }
                    if (!found) { mb[nm] = bin; mc[nm] = 1; nm++; }
                }
            }
            // aggregation rounds: match on bin, sum counts via 3 ballots
            for (int r = 0; r < 4; r++) {
                if (!__any_sync(0xffffffffu, r < nm)) break;
                bool act = r < nm;
                unsigned key = act ? mb[r] : (0x80000000u | lane);
                unsigned peers = __match_any_sync(0xffffffffu, key);
                int cnt = act ? mc[r] : 0;
                unsigned b0 = __ballot_sync(0xffffffffu, cnt & 1);
                unsigned b1 = __ballot_sync(0xffffffffu, cnt & 2);
                unsigned b2 = __ballot_sync(0xffffffffu, cnt & 4);
                if (act && lane == (unsigned)(__ffs(peers) - 1)) {
                    unsigned s = __popc(peers & b0) + 2u * __popc(peers & b1)
                               + 4u * __popc(peers & b2);
                    atomicAdd(&sh[e * 2048 + mb[r]], s);
                }
            }
        }
    }
    __syncthreads();
    unsigned* gh = &g_hist[0][0];
    for (int q = tid; q < NEPS * 2048; q += 256) {
        unsigned v = sh[q];
        if (v) atomicAdd(&gh[q], v);
    }
}

__global__ void scan_kernel(int pass) {
    int tid = threadIdx.x;              // 128 threads: warp e handles eps e
    int e = tid >> 5, lane = tid & 31;

    unsigned chunkSum = 0;
    for (int q = 0; q < 64; q++) chunkSum += g_hist[e][lane * 64 + q];

    unsigned incl = chunkSum;
    #pragma unroll
    for (int o = 1; o < 32; o <<= 1) {
        unsigned v = __shfl_up_sync(0xffffffffu, incl, o);
        if (lane >= o) incl += v;
    }
    unsigned total = __shfl_sync(0xffffffffu, incl, 31);
    unsigned exclusive = incl - chunkSum;

    if (pass == 0 && lane == 0) {
        if (total == 0) {
            g_done[e] = 1;
            g_thrbits[e] = 0x7F800000u;   // +inf
            g_pref[e] = 0xFFFFFFFFu;      // impossible prefix
        } else {
            g_done[e] = 0;
        }
    }

    bool skip = (pass > 0) && (g_done[e] != 0);
    if (!skip && total > 0) {
        unsigned k = (pass == 0) ? ((total - 1u) >> 1) : g_k[e];
        bool mine = (exclusive <= k) && (k < exclusive + chunkSum);
        if (mine) {
            unsigned cum = exclusive, b = 0;
            for (int q = 0; q < 64; q++) {
                unsigned h = g_hist[e][lane * 64 + q];
                if (cum + h > k) { b = (unsigned)(lane * 64 + q); break; }
                cum += h;
            }
            g_k[e] = k - cum;
            if (pass == 0)      g_pref[e] = b;
            else if (pass == 1) g_pref[e] = (g_pref[e] << 11) | b;
            else                g_thrbits[e] = (g_pref[e] << 9) | b;
        }
    }
    __syncthreads();
    unsigned* gh = &g_hist[0][0];
    for (int q = tid; q < NEPS * 2048; q += 128) gh[q] = 0;
}

// ---------------- Stage 4: packed adjacency bitsets (all eps, 1 d read) ----
__global__ void bits_kernel() {
    unsigned gw   = (blockIdx.x * 256u + threadIdx.x) >> 5;  // warp: (i, wc)
    unsigned lane = threadIdx.x & 31u;
    unsigned i    = gw >> 7;
    unsigned wc   = gw & 127u;
    unsigned j    = (wc << 5) + lane;

    float dv = g_d[i * NPTS + j];
    unsigned both = (unsigned)(g_vmb[i] & g_vmb[j]);
    bool offd = (i != j);

    #pragma unroll
    for (int e = 0; e < NEPS; e++) {
        float thr = __uint_as_float(g_thrbits[e]);
        bool a = (dv <= thr) && ((both >> e) & 1u) && offd;
        unsigned word = __ballot_sync(0xffffffffu, a);
        if (lane == 0) g_abits[e][(i << 7) + wc] = word;
    }
}

// ---------------- Stage 4b: compact adjacency rows by rank ------------------
__global__ void compact_kernel() {
    int i = blockIdx.x, e = blockIdx.y;
    int rk = g_rank[e][i];
    if (rk < 0) return;
    __shared__ unsigned rowbits[128];
    int t = threadIdx.x;                 // 128 threads
    rowbits[t] = g_abits[e][i * 128 + t];
    __syncthreads();
    int m = g_m[e];
    unsigned w = 0;
    int base = t * 32;
    const int* __restrict__ pl = g_plist[e];
    for (int b = 0; b < 32; b++) {
        int idx = base + b;
        if (idx < m) {
            int p = pl[idx];
            w |= ((rowbits[p >> 5] >> (p & 31)) & 1u) << b;
        }
    }
    g_cbits[e][rk * 128 + t] = w;
}

// ---------------- Stage 5: compacted (A@A) via bitset popcount --------------
// Validated 128x128 / 8x8 structure; device-side m bounds; no A masking here.
__global__ void __launch_bounds__(256, 2)
tric_kernel() {
    int bx = blockIdx.x, by = blockIdx.y, e = blockIdx.z;
    int m = g_m[e];
    int nt = (m + 127) >> 7;
    if (bx >= nt || by > bx) return;
    int kch = (m + 1023) >> 10;          // 32-word chunks actually occupied
    int i0 = by * 128, j0 = bx * 128;

    __shared__ __align__(16) unsigned char smraw[128 * 34 * 4 * 2]; // 34816 B
    unsigned* shI = (unsigned*)smraw;
    unsigned* shJ = shI + 128 * 34;
    float* stage  = (float*)smraw;       // 64*129 floats, reused after compute

    int t  = threadIdx.x;
    int tx = t & 15, ty = t >> 4;
    int acc[8][8] = {};
    const unsigned* __restrict__ Ab = g_cbits[e];
    float* __restrict__ trc = g_tric + (size_t)e * NN;

    for (int kc = 0; kc < kch; kc++) {
        #pragma unroll
        for (int r = 0; r < 16; r++) {
            int q = t + r * 256;              // 0..4095
            int row = q >> 5, w = q & 31;
            shI[row * 34 + w] = Ab[(i0 + row) * NWRD + kc * 32 + w];
        }
        #pragma unroll
        for (int r = 0; r < 16; r++) {
            int q = t + r * 256;
            int row = q >> 5, w = q & 31;
            shJ[row * 34 + w] = Ab[(j0 + row) * NWRD + kc * 32 + w];
        }
        __syncthreads();

        #pragma unroll 4
        for (int w2 = 0; w2 < 16; w2++) {
            uint2 ai[8], bj[8];
            #pragma unroll
            for (int a = 0; a < 8; a++)
                ai[a] = *(const uint2*)&shI[(ty + 16 * a) * 34 + 2 * w2];
            #pragma unroll
            for (int b = 0; b < 8; b++)
                bj[b] = *(const uint2*)&shJ[(tx + 16 * b) * 34 + 2 * w2];
            #pragma unroll
            for (int a = 0; a < 8; a++)
                #pragma unroll
                for (int b = 0; b < 8; b++)
                    acc[a][b] += __popc(ai[a].x & bj[b].x)
                               + __popc(ai[a].y & bj[b].y);
        }
        __syncthreads();
    }

    // normal-orientation write (raw counts; A-masking happens in expand)
    #pragma unroll
    for (int a = 0; a < 8; a++) {
        int il = ty + 16 * a;
        #pragma unroll
        for (int b = 0; b < 8; b++) {
            int jc = tx + 16 * b;
            trc[(unsigned)(i0 + il) * 4096u + j0 + jc] = (float)acc[a][b];
        }
    }

    if (bx != by) {
        #pragma unroll
        for (int h = 0; h < 2; h++) {
            __syncthreads();
            #pragma unroll
            for (int a = h * 4; a < h * 4 + 4; a++) {
                int il = ty + 16 * a;
                int i64 = il - h * 64;               // 0..63
                #pragma unroll
                for (int b = 0; b < 8; b++) {
                    int jc = tx + 16 * b;
                    stage[i64 * 129 + jc] = (float)acc[a][b];
                }
            }
            __syncthreads();
            #pragma unroll
            for (int a = 0; a < 8; a++) {
                int jl = ty + 16 * a;                // output row within j-tile
                #pragma unroll
                for (int b = 0; b < 4; b++) {
                    int ic = tx + 16 * b;            // 0..63
                    trc[(unsigned)(j0 + jl) * 4096u + i0 + h * 64 + ic] =
                        stage[ic * 129 + jl];
                }
            }
        }
    }
}

// ---------------- Stage 6: expand A and tri to full output ------------------
__global__ void expand_kernel(float* __restrict__ out) {
    int i = blockIdx.x, e = blockIdx.y;
    unsigned baseA = A_OFF   + (unsigned)e * 16777216u + (unsigned)i * 4096u;
    unsigned baseT = TRI_OFF + (unsigned)e * 16777216u + (unsigned)i * 4096u;
    int t = threadIdx.x;                 // 256 threads
    int mi = g_rank[e][i];

    if (mi < 0) {
        float4 z = make_float4(0.f, 0.f, 0.f, 0.f);
        #pragma unroll
        for (int q = t; q < 1024; q += 256) {
            *(float4*)&out[baseA + 4u * q] = z;
            *(float4*)&out[baseT + 4u * q] = z;
        }
        return;
    }

    __shared__ unsigned rowbits[128];
    if (t < 128) rowbits[t] = g_abits[e][i * 128 + t];
    __syncthreads();

    const float* __restrict__ trow = g_tric + (size_t)e * NN + (unsigned)mi * 4096u;
    const int4* __restrict__ rnk4 = (const int4*)g_rank[e];

    #pragma unroll
    for (int q = t; q < 1024; q += 256) {
        int4 r4 = rnk4[q];
        unsigned nib = rowbits[q >> 3] >> ((q & 7) * 4);   // 4 bits for j=4q..
        float4 a, tr;
        a.x = (nib & 1u) ? 1.f : 0.f;  tr.x = (nib & 1u) ? trow[r4.x] : 0.f;
        a.y = (nib & 2u) ? 1.f : 0.f;  tr.y = (nib & 2u) ? trow[r4.y] : 0.f;
        a.z = (nib & 4u) ? 1.f : 0.f;  tr.z = (nib & 4u) ? trow[r4.z] : 0.f;
        a.w = (nib & 8u) ? 1.f : 0.f;  tr.w = (nib & 8u) ? trow[r4.w] : 0.f;
        *(float4*)&out[baseA + 4u * q] = a;
        *(float4*)&out[baseT + 4u * q] = tr;
    }
}

// ---------------- launch ---------------------------------------------------
extern "C" void kernel_launch(void* const* d_in, const int* in_sizes, int n_in,
                              void* d_out, int out_size) {
    const float* residue    = (const float*)d_in[0];
    const float* constraint = (const float*)d_in[1];
    const float* eps        = (const float*)d_in[2];
    float* out = (float*)d_out;

    prep_kernel<<<512, 256>>>(residue, constraint, eps, out);   // launch 1
    ranks_kernel<<<1, 128>>>();                                 // launch 2

    dim3 gGrid(32, 32);
    dist_kernel<<<gGrid, 256>>>(constraint);                    // launch 3

    hzero_kernel<<<16, 256>>>(0);                               // launch 4
    hzero_kernel<<<16, 256>>>(1);                               // launch 5

    hist_kernel<0><<<2048, 256>>>();                            // launch 6 (ncu)
    scan_kernel<<<1, 128>>>(0);
    hist_kernel<1><<<2048, 256>>>();
    scan_kernel<<<1, 128>>>(1);
    hist_kernel<2><<<2048, 256>>>();
    scan_kernel<<<1, 128>>>(2);

    bits_kernel<<<65536, 256>>>();

    dim3 cGrid(4096, NEPS);
    compact_kernel<<<cGrid, 128>>>();

    dim3 tGrid(32, 32, NEPS);
    tric_kernel<<<tGrid, 256>>>();

    expand_kernel<<<cGrid, 256>>>(out);
}

// round 9
// speedup vs baseline: 2.6835x; 1.2683x over previous
#include <cuda_runtime.h>

// Problem constants
#define NPTS 4096
#define DIMK 256
#define NEPS 4
#define NWRD 128              // 4096 bits / 32 per row
#define NN   (NPTS*NPTS)      // 16777216

// Output layout (float32, concatenated in reference return order)
#define LOSS_OFF 0u
#define VM_OFF   4096u
#define A_OFF    20480u                      // 4096 + 4*4096
#define TRI_OFF  (20480u + 67108864u)        // + E*N*N

// ---------------- device scratch (globals: allocation-free rule) ----------
__device__ float         g_d[NN];                 // 67 MB distance matrix
__device__ unsigned      g_abits[NEPS][NPTS*NWRD];// 8 MB packed adjacency
__device__ unsigned      g_cbits[NEPS][NPTS*NWRD];// 8 MB compacted adjacency
__device__ float         g_tric[(size_t)NEPS*NN]; // 268 MB compacted counts
__device__ float         g_sq[NPTS];
__device__ unsigned char g_vmb[NPTS];             // 4 mask bits per point
__device__ unsigned char g_lvl[NPTS];             // first alive level (4=dead)
__device__ int           g_rank[NEPS][NPTS];      // rank among alive, -1 dead
__device__ int           g_plist[NEPS][NPTS];     // rank -> point index
__device__ int           g_m[NEPS];               // alive count
__device__ unsigned      g_hist[NEPS][2048];      // radix histograms (L or e)
__device__ unsigned      g_pref[NEPS];
__device__ unsigned      g_k[NEPS];
__device__ unsigned      g_thrbits[NEPS];
__device__ int           g_done[NEPS];

// ---------------- Stage 1: losses, vmask, sqnorms, levels -------------------
// Bit-exact XLA row-reduce: warp per row, lane-stride-32 ascending FMA, then
// shfl_down tree (16,8,4,2,1). DO NOT change the arithmetic order.
__global__ void prep_kernel(const float* __restrict__ residue,
                            const float* __restrict__ constraint,
                            const float* __restrict__ eps,
                            float* __restrict__ out) {
    int gw   = (blockIdx.x * blockDim.x + threadIdx.x) >> 5;   // row id
    int lane = threadIdx.x & 31;
    if (gw >= NPTS) return;

    const float* __restrict__ c = constraint + (unsigned)gw * DIMK;
    const float* __restrict__ r = residue    + (unsigned)gw * DIMK;

    float s_sq = 0.f, s_ls = 0.f;
    #pragma unroll
    for (int j = 0; j < 8; j++) {
        float cv = c[lane + 32 * j];
        float rv = r[lane + 32 * j];
        s_sq = __fmaf_rn(cv, cv, s_sq);
        float df = __fadd_rn(rv, -cv);
        s_ls = __fmaf_rn(df, df, s_ls);
    }
    #pragma unroll
    for (int o = 16; o > 0; o >>= 1) {
        s_sq = __fadd_rn(s_sq, __shfl_down_sync(0xffffffffu, s_sq, o));
        s_ls = __fadd_rn(s_ls, __shfl_down_sync(0xffffffffu, s_ls, o));
    }

    if (lane == 0) {
        g_sq[gw] = s_sq;
        float loss = __fsqrt_rn(s_ls);
        out[LOSS_OFF + gw] = loss;
        unsigned char mb = 0;
        #pragma unroll
        for (int e = 0; e < NEPS; e++) {
            bool m = loss <= eps[e];
            mb |= (unsigned char)((m ? 1 : 0) << e);
            out[VM_OFF + (unsigned)e * NPTS + gw] = m ? 1.f : 0.f;
        }
        g_vmb[gw] = mb;
        // epsilons ascending -> mask nested -> level = first alive eps
        g_lvl[gw] = (unsigned char)(mb ? (__ffs((int)mb) - 1) : NEPS);
    }
}

// ---------------- Stage 1b: per-eps compaction ranks ------------------------
__global__ void ranks_kernel() {
    int e = threadIdx.x >> 5, lane = threadIdx.x & 31;
    int base = lane * 128;
    int cnt = 0;
    for (int q = 0; q < 128; q++)
        cnt += (g_vmb[base + q] >> e) & 1;
    int incl = cnt;
    #pragma unroll
    for (int o = 1; o < 32; o <<= 1) {
        int v = __shfl_up_sync(0xffffffffu, incl, o);
        if (lane >= o) incl += v;
    }
    int m = __shfl_sync(0xffffffffu, incl, 31);
    int run = incl - cnt;
    for (int q = 0; q < 128; q++) {
        int idx = base + q;
        if ((g_vmb[idx] >> e) & 1) {
            g_rank[e][idx] = run;
            g_plist[e][run] = idx;
            run++;
        } else {
            g_rank[e][idx] = -1;
        }
    }
    if (lane == 0) g_m[e] = m;
}

// ---------------- Stage 2: pairwise distances (fp32, packed FFMA2) ---------
// FROZEN arithmetic per element: single accumulator, k strictly ascending,
// exact-rounded epilogue. fma.rn.f32x2 = two independent RN fp32 FMAs, so
// pairing adjacent j-columns does NOT change any element's rounding chain.
__global__ void __launch_bounds__(256, 2)
dist_kernel(const float* __restrict__ C) {
    __shared__ float shI[16 * 132];
    __shared__ float shJ[16 * 132];
    int i0 = blockIdx.y * 128, j0 = blockIdx.x * 128;
    int t  = threadIdx.x;
    int tx = t & 15, ty = t >> 4;
    unsigned long long accp[8][4] = {};   // (lo,hi) fp32 pairs, init 0.0f

    for (int k0 = 0; k0 < DIMK; k0 += 16) {
        #pragma unroll
        for (int r = 0; r < 2; r++) {
            int q   = t + r * 256;        // 0..511
            int row = q & 127;
            int kv  = q >> 7;             // 0..3 -> k offset kv*4
            float4 vI = *(const float4*)&C[(i0 + row) * DIMK + k0 + kv * 4];
            float4 vJ = *(const float4*)&C[(j0 + row) * DIMK + k0 + kv * 4];
            shI[(kv * 4 + 0) * 132 + row] = vI.x;
            shI[(kv * 4 + 1) * 132 + row] = vI.y;
            shI[(kv * 4 + 2) * 132 + row] = vI.z;
            shI[(kv * 4 + 3) * 132 + row] = vI.w;
            shJ[(kv * 4 + 0) * 132 + row] = vJ.x;
            shJ[(kv * 4 + 1) * 132 + row] = vJ.y;
            shJ[(kv * 4 + 2) * 132 + row] = vJ.z;
            shJ[(kv * 4 + 3) * 132 + row] = vJ.w;
        }
        __syncthreads();
        #pragma unroll
        for (int kk = 0; kk < 16; kk++) {
            unsigned long long aid[8], bjp[4];
            #pragma unroll
            for (int a = 0; a < 8; a++) {
                unsigned av = __float_as_uint(shI[kk * 132 + ty + 16 * a]);
                asm("mov.b64 %0, {%1, %1};" : "=l"(aid[a]) : "r"(av));
            }
            #pragma unroll
            for (int b = 0; b < 4; b++)
                bjp[b] = *(const unsigned long long*)
                             &shJ[kk * 132 + (tx + 16 * b) * 2];
            #pragma unroll
            for (int a = 0; a < 8; a++)
                #pragma unroll
                for (int b = 0; b < 4; b++)
                    asm("fma.rn.f32x2 %0, %1, %2, %3;"
                        : "=l"(accp[a][b])
                        : "l"(aid[a]), "l"(bjp[b]), "l"(accp[a][b]));
        }
        __syncthreads();
    }

    float sqi[8];
    #pragma unroll
    for (int a = 0; a < 8; a++) sqi[a] = g_sq[i0 + ty + 16 * a];

    #pragma unroll
    for (int a = 0; a < 8; a++) {
        int i = i0 + ty + 16 * a;
        #pragma unroll
        for (int b = 0; b < 4; b++) {
            unsigned lo, hi;
            asm("mov.b64 {%0, %1}, %2;" : "=r"(lo), "=r"(hi) : "l"(accp[a][b]));
            int jc = j0 + (tx + 16 * b) * 2;
            float v[2];
            float accv[2] = {__uint_as_float(lo), __uint_as_float(hi)};
            #pragma unroll
            for (int h = 0; h < 2; h++) {
                float t1 = __fadd_rn(sqi[a], g_sq[jc + h]);
                float g2 = __fmul_rn(2.0f, accv[h]);
                float d2 = __fadd_rn(t1, -g2);
                v[h] = __fsqrt_rn(fmaxf(d2, 0.0f));
            }
            *(float2*)&g_d[(unsigned)i * NPTS + jc] = make_float2(v[0], v[1]);
        }
    }
}

// ---------------- Stage 3a: pass-0 histogram keyed by (level, bin) ---------
// Nesting: pair valid for eps e  <=>  L = max(lvl_i, lvl_j) <= e.
// One histogram instead of four; scan sums L <= e.
__global__ void hist0_kernel() {
    __shared__ unsigned sh[NEPS * 2048];
    int tid = threadIdx.x;
    for (int q = tid; q < NEPS * 2048; q += 256) sh[q] = 0;
    __syncthreads();

    unsigned lane = (unsigned)(tid & 31);
    const float4* __restrict__ d4 = (const float4*)g_d;
    for (unsigned idx = blockIdx.x * 256u + tid; idx < (unsigned)(NN / 4);
         idx += gridDim.x * 256u) {
        float4 v = d4[idx];
        unsigned i  = idx >> 10;
        unsigned j4 = (idx & 1023u) * 4u;
        uchar4 lj = *(const uchar4*)&g_lvl[j4];
        unsigned li = (unsigned)g_lvl[i];
        float dv[4] = {v.x, v.y, v.z, v.w};
        unsigned lv[4] = {max(li, (unsigned)lj.x), max(li, (unsigned)lj.y),
                          max(li, (unsigned)lj.z), max(li, (unsigned)lj.w)};
        // per-lane merged (key, count) list over the 4 elements
        unsigned mb[4]; int mc[4]; int nm = 0;
        #pragma unroll
        for (int c = 0; c < 4; c++) {
            if (dv[c] > 0.f && lv[c] < (unsigned)NEPS) {
                unsigned key = lv[c] * 2048u + (__float_as_uint(dv[c]) >> 20);
                bool found = false;
                for (int q = 0; q < nm; q++)
                    if (mb[q] == key) { mc[q]++; found = true; break; }
                if (!found) { mb[nm] = key; mc[nm] = 1; nm++; }
            }
        }
        for (int r = 0; r < 4; r++) {
            if (!__any_sync(0xffffffffu, r < nm)) break;
            bool act = r < nm;
            unsigned key = act ? mb[r] : (0x80000000u | lane);
            unsigned peers = __match_any_sync(0xffffffffu, key);
            int cnt = act ? mc[r] : 0;
            unsigned b0 = __ballot_sync(0xffffffffu, cnt & 1);
            unsigned b1 = __ballot_sync(0xffffffffu, cnt & 2);
            unsigned b2 = __ballot_sync(0xffffffffu, cnt & 4);
            if (act && lane == (unsigned)(__ffs(peers) - 1)) {
                unsigned s = __popc(peers & b0) + 2u * __popc(peers & b1)
                           + 4u * __popc(peers & b2);
                atomicAdd(&sh[mb[r]], s);
            }
        }
    }
    __syncthreads();
    unsigned* gh = &g_hist[0][0];
    for (int q = tid; q < NEPS * 2048; q += 256) {
        unsigned v = sh[q];
        if (v) atomicAdd(&gh[q], v);
    }
}

// ---------------- Stage 3b: passes 1,2 — rare candidates, direct atomics ---
template<int PASS>
__global__ void hist12_kernel() {
    __shared__ unsigned sh[NEPS * 2048];
    int tid = threadIdx.x;
    for (int q = tid; q < NEPS * 2048; q += 256) sh[q] = 0;
    __syncthreads();

    unsigned pref[NEPS];
    #pragma unroll
    for (int e = 0; e < NEPS; e++) pref[e] = g_pref[e];

    const float4* __restrict__ d4 = (const float4*)g_d;
    for (unsigned idx = blockIdx.x * 256u + tid; idx < (unsigned)(NN / 4);
         idx += gridDim.x * 256u) {
        float4 v = d4[idx];
        unsigned i  = idx >> 10;
        unsigned j4 = (idx & 1023u) * 4u;
        uchar4 lj = *(const uchar4*)&g_lvl[j4];
        unsigned li = (unsigned)g_lvl[i];
        float dv[4] = {v.x, v.y, v.z, v.w};
        unsigned lv[4] = {max(li, (unsigned)lj.x), max(li, (unsigned)lj.y),
                          max(li, (unsigned)lj.z), max(li, (unsigned)lj.w)};
        #pragma unroll
        for (int c = 0; c < 4; c++) {
            if (!(dv[c] > 0.f) || lv[c] >= (unsigned)NEPS) continue;
            unsigned bits = __float_as_uint(dv[c]);
            unsigned hd   = (PASS == 1) ? (bits >> 20) : (bits >> 9);
            unsigned bin  = (PASS == 1) ? ((bits >> 9) & 2047u) : (bits & 511u);
            #pragma unroll
            for (int e = 0; e < NEPS; e++)
                if (lv[c] <= (unsigned)e && hd == pref[e])
                    atomicAdd(&sh[e * 2048 + bin], 1u);
        }
    }
    __syncthreads();
    unsigned* gh = &g_hist[0][0];
    for (int q = tid; q < NEPS * 2048; q += 256) {
        unsigned v = sh[q];
        if (v) atomicAdd(&gh[q], v);
    }
}

__global__ void scan_kernel(int pass) {
    int tid = threadIdx.x;              // 128 threads: warp e handles eps e
    int e = tid >> 5, lane = tid & 31;

    // pass 0: histogram keyed by level -> eps-e counts are sum over L<=e.
    unsigned chunkSum = 0;
    for (int q = 0; q < 64; q++) {
        unsigned hv;
        if (pass == 0) {
            hv = 0;
            for (int L = 0; L <= e; L++) hv += g_hist[L][lane * 64 + q];
        } else {
            hv = g_hist[e][lane * 64 + q];
        }
        chunkSum += hv;
    }

    unsigned incl = chunkSum;
    #pragma unroll
    for (int o = 1; o < 32; o <<= 1) {
        unsigned v = __shfl_up_sync(0xffffffffu, incl, o);
        if (lane >= o) incl += v;
    }
    unsigned total = __shfl_sync(0xffffffffu, incl, 31);
    unsigned exclusive = incl - chunkSum;

    if (pass == 0 && lane == 0) {
        if (total == 0) {
            g_done[e] = 1;
            g_thrbits[e] = 0x7F800000u;   // +inf
            g_pref[e] = 0xFFFFFFFFu;      // impossible prefix
        } else {
            g_done[e] = 0;
        }
    }

    bool skip = (pass > 0) && (g_done[e] != 0);
    if (!skip && total > 0) {
        unsigned k = (pass == 0) ? ((total - 1u) >> 1) : g_k[e];
        bool mine = (exclusive <= k) && (k < exclusive + chunkSum);
        if (mine) {
            unsigned cum = exclusive, b = 0;
            for (int q = 0; q < 64; q++) {
                unsigned h;
                if (pass == 0) {
                    h = 0;
                    for (int L = 0; L <= e; L++) h += g_hist[L][lane * 64 + q];
                } else {
                    h = g_hist[e][lane * 64 + q];
                }
                if (cum + h > k) { b = (unsigned)(lane * 64 + q); break; }
                cum += h;
            }
            g_k[e] = k - cum;
            if (pass == 0)      g_pref[e] = b;
            else if (pass == 1) g_pref[e] = (g_pref[e] << 11) | b;
            else                g_thrbits[e] = (g_pref[e] << 9) | b;
        }
    }
    __syncthreads();
    unsigned* gh = &g_hist[0][0];
    for (int q = tid; q < NEPS * 2048; q += 128) gh[q] = 0;
}

// ---------------- Stage 4: packed adjacency bitsets (all eps, 1 d read) ----
__global__ void bits_kernel() {
    unsigned gw   = (blockIdx.x * 256u + threadIdx.x) >> 5;  // warp: (i, wc)
    unsigned lane = threadIdx.x & 31u;
    unsigned i    = gw >> 7;
    unsigned wc   = gw & 127u;
    unsigned j    = (wc << 5) + lane;

    float dv = g_d[i * NPTS + j];
    unsigned both = (unsigned)(g_vmb[i] & g_vmb[j]);
    bool offd = (i != j);

    #pragma unroll
    for (int e = 0; e < NEPS; e++) {
        float thr = __uint_as_float(g_thrbits[e]);
        bool a = (dv <= thr) && ((both >> e) & 1u) && offd;
        unsigned word = __ballot_sync(0xffffffffu, a);
        if (lane == 0) g_abits[e][(i << 7) + wc] = word;
    }
}

// ---------------- Stage 4b: compact adjacency rows by rank ------------------
__global__ void compact_kernel() {
    int i = blockIdx.x, e = blockIdx.y;
    int rk = g_rank[e][i];
    if (rk < 0) return;
    __shared__ unsigned rowbits[128];
    int t = threadIdx.x;                 // 128 threads
    rowbits[t] = g_abits[e][i * 128 + t];
    __syncthreads();
    int m = g_m[e];
    unsigned w = 0;
    int base = t * 32;
    const int* __restrict__ pl = g_plist[e];
    for (int b = 0; b < 32; b++) {
        int idx = base + b;
        if (idx < m) {
            int p = pl[idx];
            w |= ((rowbits[p >> 5] >> (p & 31)) & 1u) << b;
        }
    }
    g_cbits[e][rk * 128 + t] = w;
}

// ---------------- Stage 5: compacted (A@A) via bitset popcount --------------
__global__ void __launch_bounds__(256, 2)
tric_kernel() {
    int bx = blockIdx.x, by = blockIdx.y, e = blockIdx.z;
    int m = g_m[e];
    int nt = (m + 127) >> 7;
    if (bx >= nt || by > bx) return;
    int kch = (m + 1023) >> 10;          // 32-word chunks actually occupied
    int i0 = by * 128, j0 = bx * 128;

    __shared__ __align__(16) unsigned char smraw[128 * 34 * 4 * 2]; // 34816 B
    unsigned* shI = (unsigned*)smraw;
    unsigned* shJ = shI + 128 * 34;
    float* stage  = (float*)smraw;       // 64*129 floats, reused after compute

    int t  = threadIdx.x;
    int tx = t & 15, ty = t >> 4;
    int acc[8][8] = {};
    const unsigned* __restrict__ Ab = g_cbits[e];
    float* __restrict__ trc = g_tric + (size_t)e * NN;

    for (int kc = 0; kc < kch; kc++) {
        #pragma unroll
        for (int r = 0; r < 16; r++) {
            int q = t + r * 256;              // 0..4095
            int row = q >> 5, w = q & 31;
            shI[row * 34 + w] = Ab[(i0 + row) * NWRD + kc * 32 + w];
        }
        #pragma unroll
        for (int r = 0; r < 16; r++) {
            int q = t + r * 256;
            int row = q >> 5, w = q & 31;
            shJ[row * 34 + w] = Ab[(j0 + row) * NWRD + kc * 32 + w];
        }
        __syncthreads();

        #pragma unroll 4
        for (int w2 = 0; w2 < 16; w2++) {
            uint2 ai[8], bj[8];
            #pragma unroll
            for (int a = 0; a < 8; a++)
                ai[a] = *(const uint2*)&shI[(ty + 16 * a) * 34 + 2 * w2];
            #pragma unroll
            for (int b = 0; b < 8; b++)
                bj[b] = *(const uint2*)&shJ[(tx + 16 * b) * 34 + 2 * w2];
            #pragma unroll
            for (int a = 0; a < 8; a++)
                #pragma unroll
                for (int b = 0; b < 8; b++)
                    acc[a][b] += __popc(ai[a].x & bj[b].x)
                               + __popc(ai[a].y & bj[b].y);
        }
        __syncthreads();
    }

    #pragma unroll
    for (int a = 0; a < 8; a++) {
        int il = ty + 16 * a;
        #pragma unroll
        for (int b = 0; b < 8; b++) {
            int jc = tx + 16 * b;
            trc[(unsigned)(i0 + il) * 4096u + j0 + jc] = (float)acc[a][b];
        }
    }

    if (bx != by) {
        #pragma unroll
        for (int h = 0; h < 2; h++) {
            __syncthreads();
            #pragma unroll
            for (int a = h * 4; a < h * 4 + 4; a++) {
                int il = ty + 16 * a;
                int i64 = il - h * 64;               // 0..63
                #pragma unroll
                for (int b = 0; b < 8; b++) {
                    int jc = tx + 16 * b;
                    stage[i64 * 129 + jc] = (float)acc[a][b];
                }
            }
            __syncthreads();
            #pragma unroll
            for (int a = 0; a < 8; a++) {
                int jl = ty + 16 * a;                // output row within j-tile
                #pragma unroll
                for (int b = 0; b < 4; b++) {
                    int ic = tx + 16 * b;            // 0..63
                    trc[(unsigned)(j0 + jl) * 4096u + i0 + h * 64 + ic] =
                        stage[ic * 129 + jl];
                }
            }
        }
    }
}

// ---------------- Stage 6: expand A and tri to full output ------------------
__global__ void expand_kernel(float* __restrict__ out) {
    int i = blockIdx.x, e = blockIdx.y;
    unsigned baseA = A_OFF   + (unsigned)e * 16777216u + (unsigned)i * 4096u;
    unsigned baseT = TRI_OFF + (unsigned)e * 16777216u + (unsigned)i * 4096u;
    int t = threadIdx.x;                 // 256 threads
    int mi = g_rank[e][i];

    if (mi < 0) {
        float4 z = make_float4(0.f, 0.f, 0.f, 0.f);
        #pragma unroll
        for (int q = t; q < 1024; q += 256) {
            *(float4*)&out[baseA + 4u * q] = z;
            *(float4*)&out[baseT + 4u * q] = z;
        }
        return;
    }

    __shared__ unsigned rowbits[128];
    if (t < 128) rowbits[t] = g_abits[e][i * 128 + t];
    __syncthreads();

    const float* __restrict__ trow = g_tric + (size_t)e * NN + (unsigned)mi * 4096u;
    const int4* __restrict__ rnk4 = (const int4*)g_rank[e];

    #pragma unroll
    for (int q = t; q < 1024; q += 256) {
        int4 r4 = rnk4[q];
        unsigned nib = rowbits[q >> 3] >> ((q & 7) * 4);   // 4 bits for j=4q..
        float4 a, tr;
        a.x = (nib & 1u) ? 1.f : 0.f;  tr.x = (nib & 1u) ? trow[r4.x] : 0.f;
        a.y = (nib & 2u) ? 1.f : 0.f;  tr.y = (nib & 2u) ? trow[r4.y] : 0.f;
        a.z = (nib & 4u) ? 1.f : 0.f;  tr.z = (nib & 4u) ? trow[r4.z] : 0.f;
        a.w = (nib & 8u) ? 1.f : 0.f;  tr.w = (nib & 8u) ? trow[r4.w] : 0.f;
        *(float4*)&out[baseA + 4u * q] = a;
        *(float4*)&out[baseT + 4u * q] = tr;
    }
}

// ---------------- launch ---------------------------------------------------
extern "C" void kernel_launch(void* const* d_in, const int* in_sizes, int n_in,
                              void* d_out, int out_size) {
    const float* residue    = (const float*)d_in[0];
    const float* constraint = (const float*)d_in[1];
    const float* eps        = (const float*)d_in[2];
    float* out = (float*)d_out;

    prep_kernel<<<512, 256>>>(residue, constraint, eps, out);
    ranks_kernel<<<1, 128>>>();

    dim3 gGrid(32, 32);
    dist_kernel<<<gGrid, 256>>>(constraint);

    hist0_kernel<<<2048, 256>>>();
    scan_kernel<<<1, 128>>>(0);
    hist12_kernel<1><<<2048, 256>>>();
    scan_kernel<<<1, 128>>>(1);
    hist12_kernel<2><<<2048, 256>>>();
    scan_kernel<<<1, 128>>>(2);

    bits_kernel<<<65536, 256>>>();

    dim3 cGrid(4096, NEPS);
    compact_kernel<<<cGrid, 128>>>();

    dim3 tGrid(32, 32, NEPS);
    tric_kernel<<<tGrid, 256>>>();

    expand_kernel<<<cGrid, 256>>>(out);
}

// round 11
// speedup vs baseline: 3.1772x; 1.1840x over previous
#include <cuda_runtime.h>

// Problem constants
#define NPTS 4096
#define DIMK 256
#define NEPS 4
#define NWRD 128              // 4096 bits / 32 per row
#define NN   (NPTS*NPTS)      // 16777216

// Output layout (float32, concatenated in reference return order)
#define LOSS_OFF 0u
#define VM_OFF   4096u
#define A_OFF    20480u                      // 4096 + 4*4096
#define TRI_OFF  (20480u + 67108864u)        // + E*N*N

// ---------------- device scratch (globals: allocation-free rule) ----------
__device__ float         g_d[NN];                 // 67 MB distance matrix
__device__ unsigned      g_abits[NEPS][NPTS*NWRD];// 8 MB packed adjacency
__device__ unsigned      g_cbits[NEPS][NPTS*NWRD];// 8 MB compacted adjacency
__device__ float         g_tric[(size_t)NEPS*NN]; // 268 MB compacted counts
__device__ float         g_sq[NPTS];
__device__ unsigned char g_vmb[NPTS];             // 4 mask bits per point
__device__ unsigned char g_lvl[NPTS];             // first alive level (4=dead)
__device__ int           g_rank[NEPS][NPTS];      // rank among alive, -1 dead
__device__ int           g_plist[NEPS][NPTS];     // rank -> point index
__device__ int           g_m[NEPS];               // alive count
__device__ unsigned      g_hist[NEPS][2048];      // radix histograms (L or e)
__device__ unsigned      g_pref[NEPS];
__device__ unsigned      g_k[NEPS];
__device__ unsigned      g_thrbits[NEPS];
__device__ int           g_done[NEPS];

// ---------------- Stage 1: losses, vmask, sqnorms, levels -------------------
// Bit-exact XLA row-reduce: warp per row, lane-stride-32 ascending FMA, then
// shfl_down tree (16,8,4,2,1). DO NOT change the arithmetic order.
__global__ void prep_kernel(const float* __restrict__ residue,
                            const float* __restrict__ constraint,
                            const float* __restrict__ eps,
                            float* __restrict__ out) {
    int gw   = (blockIdx.x * blockDim.x + threadIdx.x) >> 5;   // row id
    int lane = threadIdx.x & 31;
    if (gw >= NPTS) return;

    const float* __restrict__ c = constraint + (unsigned)gw * DIMK;
    const float* __restrict__ r = residue    + (unsigned)gw * DIMK;

    float s_sq = 0.f, s_ls = 0.f;
    #pragma unroll
    for (int j = 0; j < 8; j++) {
        float cv = c[lane + 32 * j];
        float rv = r[lane + 32 * j];
        s_sq = __fmaf_rn(cv, cv, s_sq);
        float df = __fadd_rn(rv, -cv);
        s_ls = __fmaf_rn(df, df, s_ls);
    }
    #pragma unroll
    for (int o = 16; o > 0; o >>= 1) {
        s_sq = __fadd_rn(s_sq, __shfl_down_sync(0xffffffffu, s_sq, o));
        s_ls = __fadd_rn(s_ls, __shfl_down_sync(0xffffffffu, s_ls, o));
    }

    if (lane == 0) {
        g_sq[gw] = s_sq;
        float loss = __fsqrt_rn(s_ls);
        out[LOSS_OFF + gw] = loss;
        unsigned char mb = 0;
        #pragma unroll
        for (int e = 0; e < NEPS; e++) {
            bool m = loss <= eps[e];
            mb |= (unsigned char)((m ? 1 : 0) << e);
            out[VM_OFF + (unsigned)e * NPTS + gw] = m ? 1.f : 0.f;
        }
        g_vmb[gw] = mb;
        g_lvl[gw] = (unsigned char)(mb ? (__ffs((int)mb) - 1) : NEPS);
    }
}

// ---------------- Stage 1b: per-eps compaction ranks ------------------------
__global__ void ranks_kernel() {
    int e = threadIdx.x >> 5, lane = threadIdx.x & 31;
    int base = lane * 128;
    int cnt = 0;
    for (int q = 0; q < 128; q++)
        cnt += (g_vmb[base + q] >> e) & 1;
    int incl = cnt;
    #pragma unroll
    for (int o = 1; o < 32; o <<= 1) {
        int v = __shfl_up_sync(0xffffffffu, incl, o);
        if (lane >= o) incl += v;
    }
    int m = __shfl_sync(0xffffffffu, incl, 31);
    int run = incl - cnt;
    for (int q = 0; q < 128; q++) {
        int idx = base + q;
        if ((g_vmb[idx] >> e) & 1) {
            g_rank[e][idx] = run;
            g_plist[e][run] = idx;
            run++;
        } else {
            g_rank[e][idx] = -1;
        }
    }
    if (lane == 0) g_m[e] = m;
}

// ---------------- Stage 2: pairwise distances (fp32, packed FFMA2) ---------
// Triangular grid: d is bit-exactly symmetric (commutative products, same
// ascending-k chain; commutative epilogue adds), so only tiles by<=bx are
// computed; the mirrored tile is written via an smem-staged transpose with
// values bit-identical to what the mirror block would have produced.
__global__ void __launch_bounds__(256, 2)
dist_kernel(const float* __restrict__ C) {
    int bx = blockIdx.x, by = blockIdx.y;
    if (by > bx) return;

    __shared__ __align__(16) float smem[64 * 129];   // 33 KB union buffer
    float* shI = smem;                  // 16*132 floats
    float* shJ = smem + 16 * 132;       // 16*132 floats
    float* stage = smem;                // 64*129 floats (post-mainloop)

    int i0 = by * 128, j0 = bx * 128;
    int t  = threadIdx.x;
    int tx = t & 15, ty = t >> 4;
    unsigned long long accp[8][4] = {};   // (lo,hi) fp32 pairs, init 0.0f

    for (int k0 = 0; k0 < DIMK; k0 += 16) {
        #pragma unroll
        for (int r = 0; r < 2; r++) {
            int q   = t + r * 256;        // 0..511
            int row = q & 127;
            int kv  = q >> 7;             // 0..3 -> k offset kv*4
            float4 vI = *(const float4*)&C[(i0 + row) * DIMK + k0 + kv * 4];
            float4 vJ = *(const float4*)&C[(j0 + row) * DIMK + k0 + kv * 4];
            shI[(kv * 4 + 0) * 132 + row] = vI.x;
            shI[(kv * 4 + 1) * 132 + row] = vI.y;
            shI[(kv * 4 + 2) * 132 + row] = vI.z;
            shI[(kv * 4 + 3) * 132 + row] = vI.w;
            shJ[(kv * 4 + 0) * 132 + row] = vJ.x;
            shJ[(kv * 4 + 1) * 132 + row] = vJ.y;
            shJ[(kv * 4 + 2) * 132 + row] = vJ.z;
            shJ[(kv * 4 + 3) * 132 + row] = vJ.w;
        }
        __syncthreads();
        #pragma unroll
        for (int kk = 0; kk < 16; kk++) {
            unsigned long long aid[8], bjp[4];
            #pragma unroll
            for (int a = 0; a < 8; a++) {
                unsigned av = __float_as_uint(shI[kk * 132 + ty + 16 * a]);
                asm("mov.b64 %0, {%1, %1};" : "=l"(aid[a]) : "r"(av));
            }
            #pragma unroll
            for (int b = 0; b < 4; b++)
                bjp[b] = *(const unsigned long long*)
                             &shJ[kk * 132 + (tx + 16 * b) * 2];
            #pragma unroll
            for (int a = 0; a < 8; a++)
                #pragma unroll
                for (int b = 0; b < 4; b++)
                    asm("fma.rn.f32x2 %0, %1, %2, %3;"
                        : "=l"(accp[a][b])
                        : "l"(aid[a]), "l"(bjp[b]), "l"(accp[a][b]));
        }
        __syncthreads();
    }

    float sqi[8];
    #pragma unroll
    for (int a = 0; a < 8; a++) sqi[a] = g_sq[i0 + ty + 16 * a];

    #pragma unroll
    for (int h = 0; h < 2; h++) {
        __syncthreads();
        // compute this half's values, write normal orientation, stage
        #pragma unroll
        for (int a4 = 0; a4 < 4; a4++) {
            int a  = h * 4 + a4;
            int il = ty + 16 * a;                   // local i row
            int i  = i0 + il;
            #pragma unroll
            for (int b = 0; b < 4; b++) {
                unsigned lo, hi;
                asm("mov.b64 {%0, %1}, %2;"
                    : "=r"(lo), "=r"(hi) : "l"(accp[a][b]));
                int jcl = (tx + 16 * b) * 2;        // local j col (even)
                int jc  = j0 + jcl;
                float accv[2] = {__uint_as_float(lo), __uint_as_float(hi)};
                float v[2];
                #pragma unroll
                for (int hh = 0; hh < 2; hh++) {
                    float t1 = __fadd_rn(sqi[a], g_sq[jc + hh]);
                    float g2 = __fmul_rn(2.0f, accv[hh]);
                    float d2 = __fadd_rn(t1, -g2);
                    v[hh] = __fsqrt_rn(fmaxf(d2, 0.0f));
                    stage[(il - h * 64) * 129 + jcl + hh] = v[hh];
                }
                *(float2*)&g_d[(unsigned)i * NPTS + jc] = make_float2(v[0], v[1]);
            }
        }
        __syncthreads();
        if (bx != by) {
            // mirrored tile: rows are j-columns, cols are this half's i rows
            #pragma unroll
            for (int a2 = 0; a2 < 8; a2++) {
                int jl = ty + 16 * a2;
                #pragma unroll
                for (int b2 = 0; b2 < 4; b2++) {
                    int ic = tx + 16 * b2;          // 0..63
                    g_d[(unsigned)(j0 + jl) * NPTS + i0 + h * 64 + ic] =
                        stage[ic * 129 + jl];
                }
            }
        }
    }
}

// ---------------- Stage 3a: pass-0 histogram, upper triangle, branchless ---
// d symmetric: count strictly-upper elements with weight 2, diagonal with 1.
// DEADLOCK FIX (round 10): the triangle skip must be WARP-UNIFORM — per-lane
// `continue` in front of full-mask collectives desynchronizes the warp and
// hangs. __all_sync keeps the skip for fully-sub-diagonal warps; straddling
// warps fall through and the per-lane weight w=0 excludes their elements.
__global__ void hist0_kernel() {
    __shared__ unsigned sh[NEPS * 2048];
    int tid = threadIdx.x;
    for (int q = tid; q < NEPS * 2048; q += 256) sh[q] = 0;
    __syncthreads();

    unsigned lane = (unsigned)(tid & 31);
    const float4* __restrict__ d4 = (const float4*)g_d;
    for (unsigned idx = blockIdx.x * 256u + tid; idx < (unsigned)(NN / 4);
         idx += gridDim.x * 256u) {
        unsigned i  = idx >> 10;
        unsigned j4 = (idx & 1023u) * 4u;
        if (__all_sync(0xffffffffu, j4 + 3u < i)) continue;  // warp-uniform skip
        float4 v = d4[idx];
        uchar4 lj = *(const uchar4*)&g_lvl[j4];
        unsigned li = (unsigned)g_lvl[i];
        float dv[4] = {v.x, v.y, v.z, v.w};
        unsigned lv[4] = {max(li, (unsigned)lj.x), max(li, (unsigned)lj.y),
                          max(li, (unsigned)lj.z), max(li, (unsigned)lj.w)};
        #pragma unroll
        for (int c = 0; c < 4; c++) {
            unsigned j = j4 + (unsigned)c;
            unsigned w = (j > i) ? 2u : ((j == i) ? 1u : 0u);
            bool valid = (w != 0u) && (dv[c] > 0.f) && (lv[c] < (unsigned)NEPS);
            unsigned key = valid
                ? (lv[c] * 2048u + (__float_as_uint(dv[c]) >> 20))
                : (0x80000000u | lane);
            unsigned wc_ = valid ? w : 0u;
            unsigned peers = __match_any_sync(0xffffffffu, key);
            unsigned b0 = __ballot_sync(0xffffffffu, wc_ & 1u);
            unsigned b1 = __ballot_sync(0xffffffffu, wc_ & 2u);
            if (valid && lane == (unsigned)(__ffs(peers) - 1)) {
                unsigned s = __popc(peers & b0) + 2u * __popc(peers & b1);
                atomicAdd(&sh[key], s);
            }
        }
    }
    __syncthreads();
    unsigned* gh = &g_hist[0][0];
    for (int q = tid; q < NEPS * 2048; q += 256) {
        unsigned v = sh[q];
        if (v) atomicAdd(&gh[q], v);
    }
}

// ---------------- Stage 3b: passes 1,2 — upper triangle, direct atomics ----
// Only atomics after the per-lane skips (no warp collectives) -> safe.
template<int PASS>
__global__ void hist12_kernel() {
    __shared__ unsigned sh[NEPS * 2048];
    int tid = threadIdx.x;
    for (int q = tid; q < NEPS * 2048; q += 256) sh[q] = 0;
    __syncthreads();

    unsigned pref[NEPS];
    #pragma unroll
    for (int e = 0; e < NEPS; e++) pref[e] = g_pref[e];

    const float4* __restrict__ d4 = (const float4*)g_d;
    for (unsigned idx = blockIdx.x * 256u + tid; idx < (unsigned)(NN / 4);
         idx += gridDim.x * 256u) {
        unsigned i  = idx >> 10;
        unsigned j4 = (idx & 1023u) * 4u;
        if (j4 + 3u < i) continue;               // per-lane ok: atomics only
        float4 v = d4[idx];
        uchar4 lj = *(const uchar4*)&g_lvl[j4];
        unsigned li = (unsigned)g_lvl[i];
        float dv[4] = {v.x, v.y, v.z, v.w};
        unsigned lv[4] = {max(li, (unsigned)lj.x), max(li, (unsigned)lj.y),
                          max(li, (unsigned)lj.z), max(li, (unsigned)lj.w)};
        #pragma unroll
        for (int c = 0; c < 4; c++) {
            unsigned j = j4 + (unsigned)c;
            unsigned w = (j > i) ? 2u : ((j == i) ? 1u : 0u);
            if (w == 0u || !(dv[c] > 0.f) || lv[c] >= (unsigned)NEPS) continue;
            unsigned bits = __float_as_uint(dv[c]);
            unsigned hd   = (PASS == 1) ? (bits >> 20) : (bits >> 9);
            unsigned bin  = (PASS == 1) ? ((bits >> 9) & 2047u) : (bits & 511u);
            #pragma unroll
            for (int e = 0; e < NEPS; e++)
                if (lv[c] <= (unsigned)e && hd == pref[e])
                    atomicAdd(&sh[e * 2048 + bin], w);
        }
    }
    __syncthreads();
    unsigned* gh = &g_hist[0][0];
    for (int q = tid; q < NEPS * 2048; q += 256) {
        unsigned v = sh[q];
        if (v) atomicAdd(&gh[q], v);
    }
}

__global__ void scan_kernel(int pass) {
    int tid = threadIdx.x;              // 128 threads: warp e handles eps e
    int e = tid >> 5, lane = tid & 31;

    // pass 0: histogram keyed by level -> eps-e counts are sum over L<=e.
    unsigned chunkSum = 0;
    for (int q = 0; q < 64; q++) {
        unsigned hv;
        if (pass == 0) {
            hv = 0;
            for (int L = 0; L <= e; L++) hv += g_hist[L][lane * 64 + q];
        } else {
            hv = g_hist[e][lane * 64 + q];
        }
        chunkSum += hv;
    }

    unsigned incl = chunkSum;
    #pragma unroll
    for (int o = 1; o < 32; o <<= 1) {
        unsigned v = __shfl_up_sync(0xffffffffu, incl, o);
        if (lane >= o) incl += v;
    }
    unsigned total = __shfl_sync(0xffffffffu, incl, 31);
    unsigned exclusive = incl - chunkSum;

    if (pass == 0 && lane == 0) {
        if (total == 0) {
            g_done[e] = 1;
            g_thrbits[e] = 0x7F800000u;   // +inf
            g_pref[e] = 0xFFFFFFFFu;      // impossible prefix
        } else {
            g_done[e] = 0;
        }
    }

    bool skip = (pass > 0) && (g_done[e] != 0);
    if (!skip && total > 0) {
        unsigned k = (pass == 0) ? ((total - 1u) >> 1) : g_k[e];
        bool mine = (exclusive <= k) && (k < exclusive + chunkSum);
        if (mine) {
            unsigned cum = exclusive, b = 0;
            for (int q = 0; q < 64; q++) {
                unsigned h;
                if (pass == 0) {
                    h = 0;
                    for (int L = 0; L <= e; L++) h += g_hist[L][lane * 64 + q];
                } else {
                    h = g_hist[e][lane * 64 + q];
                }
                if (cum + h > k) { b = (unsigned)(lane * 64 + q); break; }
                cum += h;
            }
            g_k[e] = k - cum;
            if (pass == 0)      g_pref[e] = b;
            else if (pass == 1) g_pref[e] = (g_pref[e] << 11) | b;
            else                g_thrbits[e] = (g_pref[e] << 9) | b;
        }
    }
    __syncthreads();
    unsigned* gh = &g_hist[0][0];
    for (int q = tid; q < NEPS * 2048; q += 128) gh[q] = 0;
}

// ---------------- Stage 4: packed adjacency bitsets (all eps, 1 d read) ----
__global__ void bits_kernel() {
    unsigned gw   = (blockIdx.x * 256u + threadIdx.x) >> 5;  // warp: (i, wc)
    unsigned lane = threadIdx.x & 31u;
    unsigned i    = gw >> 7;
    unsigned wc   = gw & 127u;
    unsigned j    = (wc << 5) + lane;

    float dv = g_d[i * NPTS + j];
    unsigned both = (unsigned)(g_vmb[i] & g_vmb[j]);
    bool offd = (i != j);

    #pragma unroll
    for (int e = 0; e < NEPS; e++) {
        float thr = __uint_as_float(g_thrbits[e]);
        bool a = (dv <= thr) && ((both >> e) & 1u) && offd;
        unsigned word = __ballot_sync(0xffffffffu, a);
        if (lane == 0) g_abits[e][(i << 7) + wc] = word;
    }
}

// ---------------- Stage 4b: compact adjacency rows by rank ------------------
__global__ void compact_kernel() {
    int i = blockIdx.x, e = blockIdx.y;
    int rk = g_rank[e][i];
    if (rk < 0) return;
    __shared__ unsigned rowbits[128];
    int t = threadIdx.x;                 // 128 threads
    rowbits[t] = g_abits[e][i * 128 + t];
    __syncthreads();
    int m = g_m[e];
    unsigned w = 0;
    int base = t * 32;
    const int* __restrict__ pl = g_plist[e];
    for (int b = 0; b < 32; b++) {
        int idx = base + b;
        if (idx < m) {
            int p = pl[idx];
            w |= ((rowbits[p >> 5] >> (p & 31)) & 1u) << b;
        }
    }
    g_cbits[e][rk * 128 + t] = w;
}

// ---------------- Stage 5: compacted (A@A) via bitset popcount --------------
__global__ void __launch_bounds__(256, 2)
tric_kernel() {
    int bx = blockIdx.x, by = blockIdx.y, e = blockIdx.z;
    int m = g_m[e];
    int nt = (m + 127) >> 7;
    if (bx >= nt || by > bx) return;
    int kch = (m + 1023) >> 10;          // 32-word chunks actually occupied
    int i0 = by * 128, j0 = bx * 128;

    __shared__ __align__(16) unsigned char smraw[128 * 34 * 4 * 2]; // 34816 B
    unsigned* shI = (unsigned*)smraw;
    unsigned* shJ = shI + 128 * 34;
    float* stage  = (float*)smraw;       // 64*129 floats, reused after compute

    int t  = threadIdx.x;
    int tx = t & 15, ty = t >> 4;
    int acc[8][8] = {};
    const unsigned* __restrict__ Ab = g_cbits[e];
    float* __restrict__ trc = g_tric + (size_t)e * NN;

    for (int kc = 0; kc < kch; kc++) {
        #pragma unroll
        for (int r = 0; r < 16; r++) {
            int q = t + r * 256;              // 0..4095
            int row = q >> 5, w = q & 31;
            shI[row * 34 + w] = Ab[(i0 + row) * NWRD + kc * 32 + w];
        }
        #pragma unroll
        for (int r = 0; r < 16; r++) {
            int q = t + r * 256;
            int row = q >> 5, w = q & 31;
            shJ[row * 34 + w] = Ab[(j0 + row) * NWRD + kc * 32 + w];
        }
        __syncthreads();

        #pragma unroll 4
        for (int w2 = 0; w2 < 16; w2++) {
            uint2 ai[8], bj[8];
            #pragma unroll
            for (int a = 0; a < 8; a++)
                ai[a] = *(const uint2*)&shI[(ty + 16 * a) * 34 + 2 * w2];
            #pragma unroll
            for (int b = 0; b < 8; b++)
                bj[b] = *(const uint2*)&shJ[(tx + 16 * b) * 34 + 2 * w2];
            #pragma unroll
            for (int a = 0; a < 8; a++)
                #pragma unroll
                for (int b = 0; b < 8; b++)
                    acc[a][b] += __popc(ai[a].x & bj[b].x)
                               + __popc(ai[a].y & bj[b].y);
        }
        __syncthreads();
    }

    #pragma unroll
    for (int a = 0; a < 8; a++) {
        int il = ty + 16 * a;
        #pragma unroll
        for (int b = 0; b < 8; b++) {
            int jc = tx + 16 * b;
            trc[(unsigned)(i0 + il) * 4096u + j0 + jc] = (float)acc[a][b];
        }
    }

    if (bx != by) {
        #pragma unroll
        for (int h = 0; h < 2; h++) {
            __syncthreads();
            #pragma unroll
            for (int a = h * 4; a < h * 4 + 4; a++) {
                int il = ty + 16 * a;
                int i64 = il - h * 64;               // 0..63
                #pragma unroll
                for (int b = 0; b < 8; b++) {
                    int jc = tx + 16 * b;
                    stage[i64 * 129 + jc] = (float)acc[a][b];
                }
            }
            __syncthreads();
            #pragma unroll
            for (int a = 0; a < 8; a++) {
                int jl = ty + 16 * a;                // output row within j-tile
                #pragma unroll
                for (int b = 0; b < 4; b++) {
                    int ic = tx + 16 * b;            // 0..63
                    trc[(unsigned)(j0 + jl) * 4096u + i0 + h * 64 + ic] =
                        stage[ic * 129 + jl];
                }
            }
        }
    }
}

// ---------------- Stage 6: expand A and tri to full output ------------------
__global__ void expand_kernel(float* __restrict__ out) {
    int i = blockIdx.x, e = blockIdx.y;
    unsigned baseA = A_OFF   + (unsigned)e * 16777216u + (unsigned)i * 4096u;
    unsigned baseT = TRI_OFF + (unsigned)e * 16777216u + (unsigned)i * 4096u;
    int t = threadIdx.x;                 // 256 threads
    int mi = g_rank[e][i];

    if (mi < 0) {
        float4 z = make_float4(0.f, 0.f, 0.f, 0.f);
        #pragma unroll
        for (int q = t; q < 1024; q += 256) {
            *(float4*)&out[baseA + 4u * q] = z;
            *(float4*)&out[baseT + 4u * q] = z;
        }
        return;
    }

    __shared__ unsigned rowbits[128];
    if (t < 128) rowbits[t] = g_abits[e][i * 128 + t];
    __syncthreads();

    const float* __restrict__ trow = g_tric + (size_t)e * NN + (unsigned)mi * 4096u;
    const int4* __restrict__ rnk4 = (const int4*)g_rank[e];

    #pragma unroll
    for (int q = t; q < 1024; q += 256) {
        unsigned nib = rowbits[q >> 3] >> ((q & 7) * 4);   // 4 bits for j=4q..
        float4 a, tr;
        a.x = (nib & 1u) ? 1.f : 0.f;
        a.y = (nib & 2u) ? 1.f : 0.f;
        a.z = (nib & 4u) ? 1.f : 0.f;
        a.w = (nib & 8u) ? 1.f : 0.f;
        if (nib & 15u) {
            int4 r4 = rnk4[q];
            tr.x = (nib & 1u) ? trow[r4.x] : 0.f;
            tr.y = (nib & 2u) ? trow[r4.y] : 0.f;
            tr.z = (nib & 4u) ? trow[r4.z] : 0.f;
            tr.w = (nib & 8u) ? trow[r4.w] : 0.f;
        } else {
            tr = make_float4(0.f, 0.f, 0.f, 0.f);
        }
        *(float4*)&out[baseA + 4u * q] = a;
        *(float4*)&out[baseT + 4u * q] = tr;
    }
}

// ---------------- launch ---------------------------------------------------
extern "C" void kernel_launch(void* const* d_in, const int* in_sizes, int n_in,
                              void* d_out, int out_size) {
    const float* residue    = (const float*)d_in[0];
    const float* constraint = (const float*)d_in[1];
    const float* eps        = (const float*)d_in[2];
    float* out = (float*)d_out;

    prep_kernel<<<512, 256>>>(residue, constraint, eps, out);
    ranks_kernel<<<1, 128>>>();

    dim3 gGrid(32, 32);
    dist_kernel<<<gGrid, 256>>>(constraint);

    hist0_kernel<<<2048, 256>>>();
    scan_kernel<<<1, 128>>>(0);
    hist12_kernel<1><<<2048, 256>>>();
    scan_kernel<<<1, 128>>>(1);
    hist12_kernel<2><<<2048, 256>>>();
    scan_kernel<<<1, 128>>>(2);

    bits_kernel<<<65536, 256>>>();

    dim3 cGrid(4096, NEPS);
    compact_kernel<<<cGrid, 128>>>();

    dim3 tGrid(32, 32, NEPS);
    tric_kernel<<<tGrid, 256>>>();

    expand_kernel<<<cGrid, 256>>>(out);
}